// round 8
// baseline (speedup 1.0000x reference)
#include <cuda_runtime.h>
#include <math.h>
#include <stdint.h>

// Problem constants
#define B_    16
#define C_    1024
#define T_    64
#define N_    12
#define BT_   (B_ * T_)       // 1024 frames
#define NF_   1024
#define ROWS_ (BT_ * N_)      // 12288
#define TN_   (T_ * N_)       // 768
#define NB_   2048            // fused B rows: [MwT | wg^T]

// Scratch (static device globals)
__device__ float g_feat[ROWS_ * NF_];   // feat, RNA-rounded to tf32
__device__ float g_TG[ROWS_ * NB_];     // [tM | G] fused output
__device__ float g_BigB[NB_ * NF_];     // rows 0-1023: MwT, rows 1024-2047: wg^T
__device__ float g_wtr[NF_ * NF_];      // Wtheta rounded
__device__ float g_wpr[NF_ * NF_];      // Wphi rounded
__device__ float g_vtp[NF_];
__device__ float g_vpt[NF_];
__device__ float g_bb[1];

// ---------------------------------------------------------------------------
// Helpers (baseline PTX only — no arch-'a' gated instructions)
// ---------------------------------------------------------------------------
__device__ __forceinline__ float rna_tf32(float x) {
    float r;
    asm("cvt.rna.tf32.f32 %0, %1;" : "=f"(r) : "f"(x));
    return r;
}
__device__ __forceinline__ uint32_t smem_u32(const void* p) {
    uint32_t a;
    asm("{ .reg .u64 t; cvta.to.shared.u64 t, %1; cvt.u32.u64 %0, t; }" : "=r"(a) : "l"(p));
    return a;
}
__device__ __forceinline__ void cp16(uint32_t s, const void* g) {
    asm volatile("cp.async.cg.shared.global [%0], [%1], 16;" :: "r"(s), "l"(g) : "memory");
}
#define CP_COMMIT() asm volatile("cp.async.commit_group;" ::: "memory")
#define SWZ(x) ((x) ^ (((x) >> 3) & 0x70))

__device__ __forceinline__ void ldsm4(uint32_t* r, uint32_t addr) {
    asm volatile("ldmatrix.sync.aligned.m8n8.x4.shared.b16 {%0,%1,%2,%3}, [%4];"
                 : "=r"(r[0]), "=r"(r[1]), "=r"(r[2]), "=r"(r[3]) : "r"(addr));
}
__device__ __forceinline__ void mma_tf32(float* c, const uint32_t* a, uint32_t b0, uint32_t b1) {
    asm volatile("mma.sync.aligned.m16n8k8.row.col.f32.tf32.tf32.f32 "
                 "{%0,%1,%2,%3}, {%4,%5,%6,%7}, {%8,%9}, {%0,%1,%2,%3};"
                 : "+f"(c[0]), "+f"(c[1]), "+f"(c[2]), "+f"(c[3])
                 : "r"(a[0]), "r"(a[1]), "r"(a[2]), "r"(a[3]), "r"(b0), "r"(b1));
}

#define BN 128
#define BK 32
#define STAGES 3
#define B_STAGE 16384

// ---------------------------------------------------------------------------
// Small GEMM (2 CTA/SM): C[m,n] = sum_k A[m,k]*Bm[n,k]; BMTx128 tile.
// ---------------------------------------------------------------------------
template <int BMT, bool ROUND>
__global__ void __launch_bounds__(256, 2) mma_gemm(const float* __restrict__ A,
                                                   const float* __restrict__ Bm,
                                                   float* __restrict__ C,
                                                   int K, int ldc) {
    constexpr int MT = BMT / 32;
    constexpr int ASTAGE = BMT * 128;
    extern __shared__ char smem[];
    const uint32_t sb = smem_u32(smem);
    const int tid = threadIdx.x, lane = tid & 31, wid = tid >> 5;
    const int m0 = blockIdx.y * BMT, n0 = blockIdx.x * BN;
    const int warp_m = wid & 1, warp_n = wid >> 1;

    const int r = tid >> 3;
    const int o16 = (tid & 7) << 4;
    const int c4 = (tid & 7) << 2;

    float acc[MT][4][4];
#pragma unroll
    for (int i = 0; i < MT; i++)
#pragma unroll
        for (int j = 0; j < 4; j++)
#pragma unroll
            for (int k = 0; k < 4; k++) acc[i][j][k] = 0.f;

    const int lrow = lane & 15;
    const int lcol = (lane >> 4) << 4;
    uint32_t a_base[MT], b_base[2];
#pragma unroll
    for (int mt = 0; mt < MT; mt++)
        a_base[mt] = (uint32_t)((warp_m * (BMT / 2) + mt * 16 + lrow) * 128 + lcol);
#pragma unroll
    for (int nh = 0; nh < 2; nh++)
        b_base[nh] = (uint32_t)((warp_n * 32 + nh * 16 + lrow) * 128 + lcol);

#define LOAD_STAGE(chunk, stage)                                                   \
    do {                                                                           \
        uint32_t sA = sb + (stage) * ASTAGE;                                       \
        uint32_t sB = sb + STAGES * ASTAGE + (stage) * B_STAGE;                    \
        int k0 = (chunk) * BK;                                                     \
        _Pragma("unroll") for (int t = 0; t < BMT / 32; t++) {                     \
            int rr = r + t * 32;                                                   \
            cp16(sA + SWZ((uint32_t)(rr * 128 + o16)),                             \
                 A + (size_t)(m0 + rr) * K + k0 + c4);                             \
        }                                                                          \
        _Pragma("unroll") for (int t = 0; t < 4; t++) {                            \
            int rr = r + t * 32;                                                   \
            cp16(sB + SWZ((uint32_t)(rr * 128 + o16)),                             \
                 Bm + (size_t)(n0 + rr) * K + k0 + c4);                            \
        }                                                                          \
        CP_COMMIT();                                                               \
    } while (0)

    LOAD_STAGE(0, 0);
    LOAD_STAGE(1, 1);

    const int nk = K / BK;
    for (int i = 0; i < nk; i++) {
        const int st = i % STAGES;
        if (i + 2 < nk) {
            asm volatile("cp.async.wait_group 1;" ::: "memory");
            __syncthreads();
            LOAD_STAGE(i + 2, (i + 2) % STAGES);
        } else {
            asm volatile("cp.async.wait_group 0;" ::: "memory");
            __syncthreads();
        }
        const uint32_t sA = sb + st * ASTAGE;
        const uint32_t sB = sb + STAGES * ASTAGE + st * B_STAGE;
#pragma unroll
        for (int ks = 0; ks < 4; ks++) {
            uint32_t a[MT][4], b[2][4];
#pragma unroll
            for (int nh = 0; nh < 2; nh++)
                ldsm4(b[nh], sB + SWZ(b_base[nh] + (uint32_t)(ks * 32)));
#pragma unroll
            for (int mt = 0; mt < MT; mt++)
                ldsm4(a[mt], sA + SWZ(a_base[mt] + (uint32_t)(ks * 32)));
#pragma unroll
            for (int mt = 0; mt < MT; mt++)
#pragma unroll
                for (int nt = 0; nt < 4; nt++)
                    mma_tf32(acc[mt][nt], a[mt], b[nt >> 1][nt & 1], b[nt >> 1][(nt & 1) + 2]);
        }
    }
#undef LOAD_STAGE

    const int mrow = lane >> 2;
    const int mcol = (lane & 3) << 1;
#pragma unroll
    for (int mt = 0; mt < MT; mt++) {
#pragma unroll
        for (int nt = 0; nt < 4; nt++) {
            int row = m0 + warp_m * (BMT / 2) + mt * 16 + mrow;
            int col = n0 + warp_n * 32 + nt * 8 + mcol;
            float2 v0 = make_float2(acc[mt][nt][0], acc[mt][nt][1]);
            float2 v1 = make_float2(acc[mt][nt][2], acc[mt][nt][3]);
            if (ROUND) {
                v0.x = rna_tf32(v0.x); v0.y = rna_tf32(v0.y);
                v1.x = rna_tf32(v1.x); v1.y = rna_tf32(v1.y);
            }
            *(float2*)&C[(size_t)row * ldc + col] = v0;
            *(float2*)&C[(size_t)(row + 8) * ldc + col] = v1;
        }
    }
}

// ---------------------------------------------------------------------------
// Big GEMM: 128x256 tile, warp tile 64x64, 1 CTA/SM, halved smem bytes/MAC.
// C[m,n] = sum_k A[m,k]*Bm[n,k]; M=12288, N=2048, K=1024 fixed.
// ---------------------------------------------------------------------------
#define BIG_ASTG 16384
#define BIG_BSTG 32768
#define BIG_SMEM (STAGES * (BIG_ASTG + BIG_BSTG))   // 147456

__global__ void __launch_bounds__(256, 1) mma_gemm_big(const float* __restrict__ A,
                                                       const float* __restrict__ Bm,
                                                       float* __restrict__ C) {
    const int K = NF_, ldc = NB_;
    extern __shared__ char smem[];
    const uint32_t sb = smem_u32(smem);
    const int tid = threadIdx.x, lane = tid & 31, wid = tid >> 5;
    const int m0 = blockIdx.y * 128, n0 = blockIdx.x * 256;
    const int warp_m = wid & 1, warp_n = wid >> 1;

    const int r = tid >> 3;
    const int o16 = (tid & 7) << 4;
    const int c4 = (tid & 7) << 2;

    float acc[4][8][4];
#pragma unroll
    for (int i = 0; i < 4; i++)
#pragma unroll
        for (int j = 0; j < 8; j++)
#pragma unroll
            for (int k = 0; k < 4; k++) acc[i][j][k] = 0.f;

    const int lrow = lane & 15;
    const int lcol = (lane >> 4) << 4;
    uint32_t a_base[4], b_base[4];
#pragma unroll
    for (int mt = 0; mt < 4; mt++)
        a_base[mt] = (uint32_t)((warp_m * 64 + mt * 16 + lrow) * 128 + lcol);
#pragma unroll
    for (int nh = 0; nh < 4; nh++)
        b_base[nh] = (uint32_t)((warp_n * 64 + nh * 16 + lrow) * 128 + lcol);

#define LOAD_STAGE_BIG(chunk, stage)                                               \
    do {                                                                           \
        uint32_t sA = sb + (stage) * BIG_ASTG;                                     \
        uint32_t sB = sb + STAGES * BIG_ASTG + (stage) * BIG_BSTG;                 \
        int k0 = (chunk) * BK;                                                     \
        _Pragma("unroll") for (int t = 0; t < 4; t++) {                            \
            int rr = r + t * 32;                                                   \
            cp16(sA + SWZ((uint32_t)(rr * 128 + o16)),                             \
                 A + (size_t)(m0 + rr) * K + k0 + c4);                             \
        }                                                                          \
        _Pragma("unroll") for (int t = 0; t < 8; t++) {                            \
            int rr = r + t * 32;                                                   \
            cp16(sB + SWZ((uint32_t)(rr * 128 + o16)),                             \
                 Bm + (size_t)(n0 + rr) * K + k0 + c4);                            \
        }                                                                          \
        CP_COMMIT();                                                               \
    } while (0)

    LOAD_STAGE_BIG(0, 0);
    LOAD_STAGE_BIG(1, 1);

    const int nk = K / BK;  // 32
    for (int i = 0; i < nk; i++) {
        const int st = i % STAGES;
        if (i + 2 < nk) {
            asm volatile("cp.async.wait_group 1;" ::: "memory");
            __syncthreads();
            LOAD_STAGE_BIG(i + 2, (i + 2) % STAGES);
        } else {
            asm volatile("cp.async.wait_group 0;" ::: "memory");
            __syncthreads();
        }
        const uint32_t sA = sb + st * BIG_ASTG;
        const uint32_t sB = sb + STAGES * BIG_ASTG + st * BIG_BSTG;
#pragma unroll
        for (int ks = 0; ks < 4; ks++) {
            uint32_t a[4][4], b[4][4];
#pragma unroll
            for (int nh = 0; nh < 4; nh++)
                ldsm4(b[nh], sB + SWZ(b_base[nh] + (uint32_t)(ks * 32)));
#pragma unroll
            for (int mt = 0; mt < 4; mt++)
                ldsm4(a[mt], sA + SWZ(a_base[mt] + (uint32_t)(ks * 32)));
#pragma unroll
            for (int mt = 0; mt < 4; mt++)
#pragma unroll
                for (int nt = 0; nt < 8; nt++)
                    mma_tf32(acc[mt][nt], a[mt], b[nt >> 1][nt & 1], b[nt >> 1][(nt & 1) + 2]);
        }
    }
#undef LOAD_STAGE_BIG

    const int mrow = lane >> 2;
    const int mcol = (lane & 3) << 1;
#pragma unroll
    for (int mt = 0; mt < 4; mt++) {
#pragma unroll
        for (int nt = 0; nt < 8; nt++) {
            int row = m0 + warp_m * 64 + mt * 16 + mrow;
            int col = n0 + warp_n * 64 + nt * 8 + mcol;
            *(float2*)&C[(size_t)row * ldc + col] =
                make_float2(acc[mt][nt][0], acc[mt][nt][1]);
            *(float2*)&C[(size_t)(row + 8) * ldc + col] =
                make_float2(acc[mt][nt][2], acc[mt][nt][3]);
        }
    }
}

// ---------------------------------------------------------------------------
// Fused weight prep: blocks 0-1023 round wt, 1024-2047 round wp,
// 2048-3071 transpose+round wg into g_BigB rows 1024..2047.
// ---------------------------------------------------------------------------
__global__ void prep_w(const float* __restrict__ wt, const float* __restrict__ wp,
                       const float* __restrict__ wg) {
    const int bi = blockIdx.x;
    const int tid = threadIdx.x;
    if (bi < 2048) {
        const float4* in = (bi < 1024) ? (const float4*)wt : (const float4*)wp;
        float4* outp = (bi < 1024) ? (float4*)g_wtr : (float4*)g_wpr;
        const int i = (bi & 1023) * 256 + tid;
        float4 v = in[i];
        v.x = rna_tf32(v.x); v.y = rna_tf32(v.y);
        v.z = rna_tf32(v.z); v.w = rna_tf32(v.w);
        outp[i] = v;
    } else {
        __shared__ float tile[32][33];
        const int bb = bi - 2048;
        const int k0 = (bb >> 5) * 32;
        const int n0 = (bb & 31) * 32;
        const int tx = tid & 31, ty = tid >> 5;
#pragma unroll
        for (int i = 0; i < 32; i += 8)
            tile[ty + i][tx] = wg[(size_t)(k0 + ty + i) * NF_ + n0 + tx];
        __syncthreads();
        float* dst = g_BigB + (size_t)NF_ * NF_;
#pragma unroll
        for (int i = 0; i < 32; i += 8)
            dst[(size_t)(n0 + ty + i) * NF_ + k0 + tx] = rna_tf32(tile[tx][ty + i]);
    }
}

// ---------------------------------------------------------------------------
// Transpose x[B,C,T,N] -> feat[(b*T+t)*N+n, c], rounded. float4 LDG,
// tile[tn][c] in smem, coalesced float4 STG along c.
// ---------------------------------------------------------------------------
__global__ void __launch_bounds__(256) transpose_x(const float* __restrict__ x) {
    __shared__ float tile[128][33];
    const int b = blockIdx.z;
    const int c0 = blockIdx.y * 32;
    const int tn0 = blockIdx.x * 128;
    const int tid = threadIdx.x;
    const int lane = tid & 31, wid = tid >> 5;

    // load: 32 c-rows x 128 tn; each pass 8 c-rows (warp per row, float4/lane)
#pragma unroll
    for (int p = 0; p < 4; p++) {
        const int c = wid + p * 8;
        float4 v = *(const float4*)(x + ((size_t)b * C_ + c0 + c) * TN_ + tn0 + lane * 4);
        tile[lane * 4 + 0][c] = v.x;
        tile[lane * 4 + 1][c] = v.y;
        tile[lane * 4 + 2][c] = v.z;
        tile[lane * 4 + 3][c] = v.w;
    }
    __syncthreads();

    // store: warp covers 4 tn rows x 32 c (8 lanes x float4 each)
    const int cc = (lane & 7) * 4;
    const int tnw = wid * 4 + (lane >> 3);
#pragma unroll
    for (int p = 0; p < 4; p++) {
        const int tn = tnw + p * 32;
        float4 v;
        v.x = rna_tf32(tile[tn][cc + 0]);
        v.y = rna_tf32(tile[tn][cc + 1]);
        v.z = rna_tf32(tile[tn][cc + 2]);
        v.w = rna_tf32(tile[tn][cc + 3]);
        *(float4*)&g_feat[((size_t)b * TN_ + tn0 + tn) * NF_ + c0 + cc] = v;
    }
}

// ---------------------------------------------------------------------------
// Bias cross-term vectors (exact fp32) — warp-per-column, coalesced
// ---------------------------------------------------------------------------
__global__ void bias_vecs(const float* __restrict__ wt, const float* __restrict__ bt,
                          const float* __restrict__ wp, const float* __restrict__ bp) {
    const int lane = threadIdx.x & 31;
    const int warp = threadIdx.x >> 5;
    const int c = blockIdx.x * 8 + warp;

    const float* wtr = wt + (size_t)c * NF_;
    const float* wpr = wp + (size_t)c * NF_;
    float a = 0.f, b2 = 0.f;
#pragma unroll
    for (int i = 0; i < 32; i++) {
        const int k = lane + 32 * i;
        a  += wtr[k] * bp[k];
        b2 += wpr[k] * bt[k];
    }
#pragma unroll
    for (int o = 16; o > 0; o >>= 1) {
        a  += __shfl_xor_sync(0xffffffffu, a, o);
        b2 += __shfl_xor_sync(0xffffffffu, b2, o);
    }
    if (lane == 0) { g_vtp[c] = a; g_vpt[c] = b2; }

    if (blockIdx.x == 0 && warp == 0) {
        float s = 0.f;
#pragma unroll
        for (int i = 0; i < 32; i++) {
            const int k = lane + 32 * i;
            s += bt[k] * bp[k];
        }
#pragma unroll
        for (int o = 16; o > 0; o >>= 1) s += __shfl_xor_sync(0xffffffffu, s, o);
        if (lane == 0) g_bb[0] = s;
    }
}

// ---------------------------------------------------------------------------
__device__ __forceinline__ float blockSum512(float v, float* red) {
    const int lane = threadIdx.x & 31, warp = threadIdx.x >> 5;
#pragma unroll
    for (int o = 16; o > 0; o >>= 1) v += __shfl_xor_sync(0xffffffffu, v, o);
    if (lane == 0) red[warp] = v;
    __syncthreads();
    if (threadIdx.x == 0) {
        float s = 0.f;
        for (int i = 0; i < 16; i++) s += red[i];
        red[16] = s;
    }
    __syncthreads();
    float r = red[16];
    __syncthreads();
    return r;
}

__device__ __forceinline__ float dot4(float4 a, float4 b) {
    return a.x * b.x + a.y * b.y + a.z * b.z + a.w * b.w;
}

__global__ void __launch_bounds__(512) frame_kernel(const float* __restrict__ Abox,
                                                    const float* __restrict__ ln_w,
                                                    const float* __restrict__ ln_b,
                                                    float* __restrict__ out,
                                                    float* __restrict__ rg_out) {
    const int f = blockIdx.x;
    const int tid = threadIdx.x;
    const int lane = tid & 31, warp = tid >> 5;

    __shared__ float px[12], py[12], sqs[12];
    __shared__ float s_u[12], s_v[12];
    __shared__ float s_rg[12][12];
    __shared__ float red[17];

    if (tid < 12) {
        const float* bx = Abox + ((size_t)f * 12 + tid) * 4;
        float cx = (bx[0] + bx[2]) * 0.5f;
        float cy = (bx[1] + bx[3]) * 0.5f;
        px[tid] = cx; py[tid] = cy; sqs[tid] = cx * cx + cy * cy;
    }

    if (warp < 12) {
        const float4* frow = (const float4*)(g_feat + ((size_t)f * 12 + warp) * NF_);
        const float4* vt4 = (const float4*)g_vtp;
        const float4* vp4 = (const float4*)g_vpt;
        float ua = 0.f, va = 0.f;
#pragma unroll
        for (int k = 0; k < 8; k++) {
            float4 fv = frow[lane + 32 * k];
            ua += dot4(fv, vt4[lane + 32 * k]);
            va += dot4(fv, vp4[lane + 32 * k]);
        }
#pragma unroll
        for (int o = 16; o > 0; o >>= 1) {
            ua += __shfl_xor_sync(0xffffffffu, ua, o);
            va += __shfl_xor_sync(0xffffffffu, va, o);
        }
        if (lane == 0) { s_u[warp] = ua; s_v[warp] = va; }
    }
    __syncthreads();

    if (warp < 12) {
        const int n = warp;
        const float4* tM4 = (const float4*)(g_TG + ((size_t)f * 12 + n) * NB_);
        float4 tr[8];
#pragma unroll
        for (int k = 0; k < 8; k++) tr[k] = tM4[lane + 32 * k];
        float lg[12];
#pragma unroll
        for (int m = 0; m < 12; m++) {
            const float4* fm4 = (const float4*)(g_feat + ((size_t)f * 12 + m) * NF_);
            float a = 0.f;
#pragma unroll
            for (int k = 0; k < 8; k++) a += dot4(tr[k], fm4[lane + 32 * k]);
#pragma unroll
            for (int o = 16; o > 0; o >>= 1) a += __shfl_xor_sync(0xffffffffu, a, o);
            lg[m] = a;
        }
        if (lane == 0) {
            const float bb = g_bb[0];
            const float scale = 0.03125f;
            float e[12];
            bool msk[12];
            float mx = -INFINITY;
#pragma unroll
            for (int m = 0; m < 12; m++) {
                float d2 = sqs[n] - 2.f * (px[n] * px[m] + py[n] * py[m]) + sqs[m];
                d2 = fmaxf(d2, 0.f);
                float dist = sqrtf(d2);
                msk[m] = (dist > 0.4f);
                float v = (lg[m] + s_u[n] + s_v[m] + bb) * scale;
                e[m] = v;
                if (!msk[m]) mx = fmaxf(mx, v);
            }
            float se = 0.f;
#pragma unroll
            for (int m = 0; m < 12; m++) {
                float ev = msk[m] ? 0.f : expf(e[m] - mx);
                e[m] = ev;
                se += ev;
            }
            float inv = 1.f / se;
#pragma unroll
            for (int m = 0; m < 12; m++) {
                float r = e[m] * inv;
                s_rg[n][m] = r;
                if (rg_out) rg_out[((size_t)f * 12 + n) * 12 + m] = r;
            }
        }
    }
    __syncthreads();

    float2 aggv[12];
    {
        float2 gv[12];
#pragma unroll
        for (int m = 0; m < 12; m++)
            gv[m] = ((const float2*)(g_TG + ((size_t)f * 12 + m) * NB_ + NF_))[tid];
#pragma unroll
        for (int n = 0; n < 12; n++) {
            float ax = 0.f, ay = 0.f;
#pragma unroll
            for (int m = 0; m < 12; m++) {
                float w = s_rg[n][m];
                ax += w * gv[m].x;
                ay += w * gv[m].y;
            }
            aggv[n] = make_float2(ax, ay);
        }
    }
    float lsum = 0.f;
#pragma unroll
    for (int n = 0; n < 12; n++) lsum += aggv[n].x + aggv[n].y;
    const float mu = blockSum512(lsum, red) * (1.f / 12288.f);

    float lsq = 0.f;
#pragma unroll
    for (int n = 0; n < 12; n++) {
        float dx = aggv[n].x - mu, dy = aggv[n].y - mu;
        lsq += dx * dx + dy * dy;
    }
    const float var = blockSum512(lsq, red) * (1.f / 12288.f);
    const float rstd = rsqrtf(var + 1e-5f);

    const float2* lw2 = (const float2*)ln_w;
    const float2* lb2 = (const float2*)ln_b;
    float2* out2 = (float2*)out;
#pragma unroll
    for (int n = 0; n < 12; n++) {
        float2 w = lw2[n * 512 + tid];
        float2 b = lb2[n * 512 + tid];
        float yx = (aggv[n].x - mu) * rstd * w.x + b.x;
        float yy = (aggv[n].y - mu) * rstd * w.y + b.y;
        out2[((size_t)f * 12 + n) * 512 + tid] = make_float2(fmaxf(yx, 0.f), fmaxf(yy, 0.f));
    }
}

// ---------------------------------------------------------------------------
extern "C" void kernel_launch(void* const* d_in, const int* in_sizes, int n_in,
                              void* d_out, int out_size) {
    const float* x  = (const float*)d_in[0];
    const float* A  = (const float*)d_in[1];
    const float* wt = (const float*)d_in[2];
    const float* bt = (const float*)d_in[3];
    const float* wp = (const float*)d_in[4];
    const float* bp = (const float*)d_in[5];
    const float* wg = (const float*)d_in[6];
    const float* lw = (const float*)d_in[7];
    const float* lb = (const float*)d_in[8];

    float* out = (float*)d_out;
    float* rg = (out_size >= (int)(ROWS_ * NF_ + BT_ * N_ * N_))
                    ? out + (size_t)ROWS_ * NF_
                    : nullptr;

    float *feat, *TG, *BigB, *wtr, *wpr;
    cudaGetSymbolAddress((void**)&feat, g_feat);
    cudaGetSymbolAddress((void**)&TG, g_TG);
    cudaGetSymbolAddress((void**)&BigB, g_BigB);
    cudaGetSymbolAddress((void**)&wtr, g_wtr);
    cudaGetSymbolAddress((void**)&wpr, g_wpr);

    const int smem_small = STAGES * (64 * 128 + B_STAGE);    // 73728
    cudaFuncSetAttribute(mma_gemm<64, true>,
                         cudaFuncAttributeMaxDynamicSharedMemorySize, smem_small);
    cudaFuncSetAttribute(mma_gemm_big,
                         cudaFuncAttributeMaxDynamicSharedMemorySize, BIG_SMEM);

    // Launch order: big GEMM is launch #4 (ncu consistently profiles #4)
    prep_w<<<3072, 256>>>(wt, wp, wg);                                       // 1
    transpose_x<<<dim3(TN_ / 128, NF_ / 32, B_), 256>>>(x);                  // 2
    // MwT[n,k] = sum_r wphi[n,r]*wtheta[k,r] -> BigB rows 0..1023 (rounded)
    mma_gemm<64, true><<<dim3(NF_ / BN, NF_ / 64), 256, smem_small>>>(       // 3
        wpr, wtr, BigB, NF_, NF_);
    // [tM | G] = feat @ [MwT | wg^T]^T   (fused, N = 2048)
    mma_gemm_big<<<dim3(NB_ / 256, ROWS_ / 128), 256, BIG_SMEM>>>(           // 4
        feat, BigB, TG);

    bias_vecs<<<128, 256>>>(wt, bt, wp, bp);                                 // 5
    frame_kernel<<<BT_, 512>>>(A, lw, lb, out, rg);                          // 6
}

// round 9
// speedup vs baseline: 1.1033x; 1.1033x over previous
#include <cuda_runtime.h>
#include <math.h>
#include <stdint.h>

// Problem constants
#define B_    16
#define C_    1024
#define T_    64
#define N_    12
#define BT_   (B_ * T_)       // 1024 frames
#define NF_   1024
#define ROWS_ (BT_ * N_)      // 12288
#define TN_   (T_ * N_)       // 768
#define NB_   2048            // fused B rows: [MwT | wg^T]

// Scratch (static device globals)
__device__ float g_feat[ROWS_ * NF_];   // feat, RNA-rounded to tf32
__device__ float g_TG[ROWS_ * NB_];     // [tM | G] fused output
__device__ float g_BigB[NB_ * NF_];     // rows 0-1023: MwT, rows 1024-2047: wg^T
__device__ float g_wtr[NF_ * NF_];      // Wtheta rounded
__device__ float g_wpr[NF_ * NF_];      // Wphi rounded
__device__ float g_vtp[NF_];
__device__ float g_vpt[NF_];
__device__ float g_bb[1];

// ---------------------------------------------------------------------------
// Helpers (baseline PTX only — no arch-'a' gated instructions)
// ---------------------------------------------------------------------------
__device__ __forceinline__ float rna_tf32(float x) {
    float r;
    asm("cvt.rna.tf32.f32 %0, %1;" : "=f"(r) : "f"(x));
    return r;
}
__device__ __forceinline__ uint32_t smem_u32(const void* p) {
    uint32_t a;
    asm("{ .reg .u64 t; cvta.to.shared.u64 t, %1; cvt.u32.u64 %0, t; }" : "=r"(a) : "l"(p));
    return a;
}
__device__ __forceinline__ void cp16(uint32_t s, const void* g) {
    asm volatile("cp.async.cg.shared.global [%0], [%1], 16;" :: "r"(s), "l"(g) : "memory");
}
#define CP_COMMIT() asm volatile("cp.async.commit_group;" ::: "memory")
#define SWZ(x) ((x) ^ (((x) >> 3) & 0x70))

__device__ __forceinline__ void ldsm4(uint32_t* r, uint32_t addr) {
    asm volatile("ldmatrix.sync.aligned.m8n8.x4.shared.b16 {%0,%1,%2,%3}, [%4];"
                 : "=r"(r[0]), "=r"(r[1]), "=r"(r[2]), "=r"(r[3]) : "r"(addr));
}
__device__ __forceinline__ void mma_tf32(float* c, const uint32_t* a, uint32_t b0, uint32_t b1) {
    asm volatile("mma.sync.aligned.m16n8k8.row.col.f32.tf32.tf32.f32 "
                 "{%0,%1,%2,%3}, {%4,%5,%6,%7}, {%8,%9}, {%0,%1,%2,%3};"
                 : "+f"(c[0]), "+f"(c[1]), "+f"(c[2]), "+f"(c[3])
                 : "r"(a[0]), "r"(a[1]), "r"(a[2]), "r"(a[3]), "r"(b0), "r"(b1));
}

#define BN 128
#define BK 32
#define STAGES 3
#define B_STAGE 16384

// ---------------------------------------------------------------------------
// Small GEMM (2 CTA/SM): C[m,n] = sum_k A[m,k]*Bm[n,k]; BMTx128 tile.
// ---------------------------------------------------------------------------
template <int BMT, bool ROUND>
__global__ void __launch_bounds__(256, 2) mma_gemm(const float* __restrict__ A,
                                                   const float* __restrict__ Bm,
                                                   float* __restrict__ C,
                                                   int K, int ldc) {
    constexpr int MT = BMT / 32;
    constexpr int ASTAGE = BMT * 128;
    extern __shared__ char smem[];
    const uint32_t sb = smem_u32(smem);
    const int tid = threadIdx.x, lane = tid & 31, wid = tid >> 5;
    const int m0 = blockIdx.y * BMT, n0 = blockIdx.x * BN;
    const int warp_m = wid & 1, warp_n = wid >> 1;

    const int r = tid >> 3;
    const int o16 = (tid & 7) << 4;
    const int c4 = (tid & 7) << 2;

    float acc[MT][4][4];
#pragma unroll
    for (int i = 0; i < MT; i++)
#pragma unroll
        for (int j = 0; j < 4; j++)
#pragma unroll
            for (int k = 0; k < 4; k++) acc[i][j][k] = 0.f;

    const int lrow = lane & 15;
    const int lcol = (lane >> 4) << 4;
    uint32_t a_base[MT], b_base[2];
#pragma unroll
    for (int mt = 0; mt < MT; mt++)
        a_base[mt] = (uint32_t)((warp_m * (BMT / 2) + mt * 16 + lrow) * 128 + lcol);
#pragma unroll
    for (int nh = 0; nh < 2; nh++)
        b_base[nh] = (uint32_t)((warp_n * 32 + nh * 16 + lrow) * 128 + lcol);

#define LOAD_STAGE(chunk, stage)                                                   \
    do {                                                                           \
        uint32_t sA = sb + (stage) * ASTAGE;                                       \
        uint32_t sB = sb + STAGES * ASTAGE + (stage) * B_STAGE;                    \
        int k0 = (chunk) * BK;                                                     \
        _Pragma("unroll") for (int t = 0; t < BMT / 32; t++) {                     \
            int rr = r + t * 32;                                                   \
            cp16(sA + SWZ((uint32_t)(rr * 128 + o16)),                             \
                 A + (size_t)(m0 + rr) * K + k0 + c4);                             \
        }                                                                          \
        _Pragma("unroll") for (int t = 0; t < 4; t++) {                            \
            int rr = r + t * 32;                                                   \
            cp16(sB + SWZ((uint32_t)(rr * 128 + o16)),                             \
                 Bm + (size_t)(n0 + rr) * K + k0 + c4);                            \
        }                                                                          \
        CP_COMMIT();                                                               \
    } while (0)

    LOAD_STAGE(0, 0);
    LOAD_STAGE(1, 1);

    const int nk = K / BK;
    for (int i = 0; i < nk; i++) {
        const int st = i % STAGES;
        if (i + 2 < nk) {
            asm volatile("cp.async.wait_group 1;" ::: "memory");
            __syncthreads();
            LOAD_STAGE(i + 2, (i + 2) % STAGES);
        } else {
            asm volatile("cp.async.wait_group 0;" ::: "memory");
            __syncthreads();
        }
        const uint32_t sA = sb + st * ASTAGE;
        const uint32_t sB = sb + STAGES * ASTAGE + st * B_STAGE;
#pragma unroll
        for (int ks = 0; ks < 4; ks++) {
            uint32_t a[MT][4], b[2][4];
#pragma unroll
            for (int nh = 0; nh < 2; nh++)
                ldsm4(b[nh], sB + SWZ(b_base[nh] + (uint32_t)(ks * 32)));
#pragma unroll
            for (int mt = 0; mt < MT; mt++)
                ldsm4(a[mt], sA + SWZ(a_base[mt] + (uint32_t)(ks * 32)));
#pragma unroll
            for (int mt = 0; mt < MT; mt++)
#pragma unroll
                for (int nt = 0; nt < 4; nt++)
                    mma_tf32(acc[mt][nt], a[mt], b[nt >> 1][nt & 1], b[nt >> 1][(nt & 1) + 2]);
        }
    }
#undef LOAD_STAGE

    const int mrow = lane >> 2;
    const int mcol = (lane & 3) << 1;
#pragma unroll
    for (int mt = 0; mt < MT; mt++) {
#pragma unroll
        for (int nt = 0; nt < 4; nt++) {
            int row = m0 + warp_m * (BMT / 2) + mt * 16 + mrow;
            int col = n0 + warp_n * 32 + nt * 8 + mcol;
            float2 v0 = make_float2(acc[mt][nt][0], acc[mt][nt][1]);
            float2 v1 = make_float2(acc[mt][nt][2], acc[mt][nt][3]);
            if (ROUND) {
                v0.x = rna_tf32(v0.x); v0.y = rna_tf32(v0.y);
                v1.x = rna_tf32(v1.x); v1.y = rna_tf32(v1.y);
            }
            *(float2*)&C[(size_t)row * ldc + col] = v0;
            *(float2*)&C[(size_t)(row + 8) * ldc + col] = v1;
        }
    }
}

// ---------------------------------------------------------------------------
// Big GEMM: 128 threads (4 warps), CTA tile 128x128, warp tile 64x64,
// 3-stage cp.async (96KB) -> 2 CTA/SM. Low bytes/MAC AND barrier overlap.
// C[m,n] = sum_k A[m,k]*Bm[n,k]; M=12288, N=2048, K=1024 fixed.
// ---------------------------------------------------------------------------
#define BIG_STG 16384
#define BIG_SMEM (STAGES * 2 * BIG_STG)   // 98304

__global__ void __launch_bounds__(128, 2) mma_gemm_big(const float* __restrict__ A,
                                                       const float* __restrict__ Bm,
                                                       float* __restrict__ C) {
    const int K = NF_, ldc = NB_;
    extern __shared__ char smem[];
    const uint32_t sb = smem_u32(smem);
    const int tid = threadIdx.x, lane = tid & 31, wid = tid >> 5;
    const int m0 = blockIdx.y * 128, n0 = blockIdx.x * 128;
    const int warp_m = wid & 1, warp_n = wid >> 1;   // 2x2 warps, 64x64 each

    // cp.async tiling: 8 threads x 16B per 128B row, 16 rows per pass (128 thr)
    const int r = tid >> 3;
    const int o16 = (tid & 7) << 4;
    const int c4 = (tid & 7) << 2;

    float acc[4][8][4];
#pragma unroll
    for (int i = 0; i < 4; i++)
#pragma unroll
        for (int j = 0; j < 8; j++)
#pragma unroll
            for (int k = 0; k < 4; k++) acc[i][j][k] = 0.f;

    const int lrow = lane & 15;
    const int lcol = (lane >> 4) << 4;
    uint32_t a_base[4], b_base[4];
#pragma unroll
    for (int mt = 0; mt < 4; mt++)
        a_base[mt] = (uint32_t)((warp_m * 64 + mt * 16 + lrow) * 128 + lcol);
#pragma unroll
    for (int nh = 0; nh < 4; nh++)
        b_base[nh] = (uint32_t)((warp_n * 64 + nh * 16 + lrow) * 128 + lcol);

#define LOAD_STAGE_BIG(chunk, stage)                                               \
    do {                                                                           \
        uint32_t sA = sb + (stage) * BIG_STG;                                      \
        uint32_t sB = sb + STAGES * BIG_STG + (stage) * BIG_STG;                   \
        int k0 = (chunk) * BK;                                                     \
        _Pragma("unroll") for (int t = 0; t < 8; t++) {                            \
            int rr = r + t * 16;                                                   \
            cp16(sA + SWZ((uint32_t)(rr * 128 + o16)),                             \
                 A + (size_t)(m0 + rr) * K + k0 + c4);                             \
        }                                                                          \
        _Pragma("unroll") for (int t = 0; t < 8; t++) {                            \
            int rr = r + t * 16;                                                   \
            cp16(sB + SWZ((uint32_t)(rr * 128 + o16)),                             \
                 Bm + (size_t)(n0 + rr) * K + k0 + c4);                            \
        }                                                                          \
        CP_COMMIT();                                                               \
    } while (0)

    LOAD_STAGE_BIG(0, 0);
    LOAD_STAGE_BIG(1, 1);

    const int nk = K / BK;  // 32
    for (int i = 0; i < nk; i++) {
        const int st = i % STAGES;
        if (i + 2 < nk) {
            asm volatile("cp.async.wait_group 1;" ::: "memory");
            __syncthreads();
            LOAD_STAGE_BIG(i + 2, (i + 2) % STAGES);
        } else {
            asm volatile("cp.async.wait_group 0;" ::: "memory");
            __syncthreads();
        }
        const uint32_t sA = sb + st * BIG_STG;
        const uint32_t sB = sb + STAGES * BIG_STG + st * BIG_STG;
#pragma unroll
        for (int ks = 0; ks < 4; ks++) {
            uint32_t a[4][4], b[4][4];
#pragma unroll
            for (int nh = 0; nh < 4; nh++)
                ldsm4(b[nh], sB + SWZ(b_base[nh] + (uint32_t)(ks * 32)));
#pragma unroll
            for (int mt = 0; mt < 4; mt++)
                ldsm4(a[mt], sA + SWZ(a_base[mt] + (uint32_t)(ks * 32)));
#pragma unroll
            for (int mt = 0; mt < 4; mt++)
#pragma unroll
                for (int nt = 0; nt < 8; nt++)
                    mma_tf32(acc[mt][nt], a[mt], b[nt >> 1][nt & 1], b[nt >> 1][(nt & 1) + 2]);
        }
    }
#undef LOAD_STAGE_BIG

    const int mrow = lane >> 2;
    const int mcol = (lane & 3) << 1;
#pragma unroll
    for (int mt = 0; mt < 4; mt++) {
#pragma unroll
        for (int nt = 0; nt < 8; nt++) {
            int row = m0 + warp_m * 64 + mt * 16 + mrow;
            int col = n0 + warp_n * 64 + nt * 8 + mcol;
            *(float2*)&C[(size_t)row * ldc + col] =
                make_float2(acc[mt][nt][0], acc[mt][nt][1]);
            *(float2*)&C[(size_t)(row + 8) * ldc + col] =
                make_float2(acc[mt][nt][2], acc[mt][nt][3]);
        }
    }
}

// ---------------------------------------------------------------------------
// Fused weight prep: blocks 0-1023 round wt, 1024-2047 round wp,
// 2048-3071 transpose+round wg into g_BigB rows 1024..2047.
// ---------------------------------------------------------------------------
__global__ void prep_w(const float* __restrict__ wt, const float* __restrict__ wp,
                       const float* __restrict__ wg) {
    const int bi = blockIdx.x;
    const int tid = threadIdx.x;
    if (bi < 2048) {
        const float4* in = (bi < 1024) ? (const float4*)wt : (const float4*)wp;
        float4* outp = (bi < 1024) ? (float4*)g_wtr : (float4*)g_wpr;
        const int i = (bi & 1023) * 256 + tid;
        float4 v = in[i];
        v.x = rna_tf32(v.x); v.y = rna_tf32(v.y);
        v.z = rna_tf32(v.z); v.w = rna_tf32(v.w);
        outp[i] = v;
    } else {
        __shared__ float tile[32][33];
        const int bb = bi - 2048;
        const int k0 = (bb >> 5) * 32;
        const int n0 = (bb & 31) * 32;
        const int tx = tid & 31, ty = tid >> 5;
#pragma unroll
        for (int i = 0; i < 32; i += 8)
            tile[ty + i][tx] = wg[(size_t)(k0 + ty + i) * NF_ + n0 + tx];
        __syncthreads();
        float* dst = g_BigB + (size_t)NF_ * NF_;
#pragma unroll
        for (int i = 0; i < 32; i += 8)
            dst[(size_t)(n0 + ty + i) * NF_ + k0 + tx] = rna_tf32(tile[tx][ty + i]);
    }
}

// ---------------------------------------------------------------------------
// Transpose x[B,C,T,N] -> feat[(b*T+t)*N+n, c], rounded. float4 LDG,
// tile[tn][c] in smem, coalesced float4 STG along c.
// ---------------------------------------------------------------------------
__global__ void __launch_bounds__(256) transpose_x(const float* __restrict__ x) {
    __shared__ float tile[128][33];
    const int b = blockIdx.z;
    const int c0 = blockIdx.y * 32;
    const int tn0 = blockIdx.x * 128;
    const int tid = threadIdx.x;
    const int lane = tid & 31, wid = tid >> 5;

#pragma unroll
    for (int p = 0; p < 4; p++) {
        const int c = wid + p * 8;
        float4 v = *(const float4*)(x + ((size_t)b * C_ + c0 + c) * TN_ + tn0 + lane * 4);
        tile[lane * 4 + 0][c] = v.x;
        tile[lane * 4 + 1][c] = v.y;
        tile[lane * 4 + 2][c] = v.z;
        tile[lane * 4 + 3][c] = v.w;
    }
    __syncthreads();

    const int cc = (lane & 7) * 4;
    const int tnw = wid * 4 + (lane >> 3);
#pragma unroll
    for (int p = 0; p < 4; p++) {
        const int tn = tnw + p * 32;
        float4 v;
        v.x = rna_tf32(tile[tn][cc + 0]);
        v.y = rna_tf32(tile[tn][cc + 1]);
        v.z = rna_tf32(tile[tn][cc + 2]);
        v.w = rna_tf32(tile[tn][cc + 3]);
        *(float4*)&g_feat[((size_t)b * TN_ + tn0 + tn) * NF_ + c0 + cc] = v;
    }
}

// ---------------------------------------------------------------------------
// Bias cross-term vectors (exact fp32) — warp-per-column, coalesced
// ---------------------------------------------------------------------------
__global__ void bias_vecs(const float* __restrict__ wt, const float* __restrict__ bt,
                          const float* __restrict__ wp, const float* __restrict__ bp) {
    const int lane = threadIdx.x & 31;
    const int warp = threadIdx.x >> 5;
    const int c = blockIdx.x * 8 + warp;

    const float* wtr = wt + (size_t)c * NF_;
    const float* wpr = wp + (size_t)c * NF_;
    float a = 0.f, b2 = 0.f;
#pragma unroll
    for (int i = 0; i < 32; i++) {
        const int k = lane + 32 * i;
        a  += wtr[k] * bp[k];
        b2 += wpr[k] * bt[k];
    }
#pragma unroll
    for (int o = 16; o > 0; o >>= 1) {
        a  += __shfl_xor_sync(0xffffffffu, a, o);
        b2 += __shfl_xor_sync(0xffffffffu, b2, o);
    }
    if (lane == 0) { g_vtp[c] = a; g_vpt[c] = b2; }

    if (blockIdx.x == 0 && warp == 0) {
        float s = 0.f;
#pragma unroll
        for (int i = 0; i < 32; i++) {
            const int k = lane + 32 * i;
            s += bt[k] * bp[k];
        }
#pragma unroll
        for (int o = 16; o > 0; o >>= 1) s += __shfl_xor_sync(0xffffffffu, s, o);
        if (lane == 0) g_bb[0] = s;
    }
}

// ---------------------------------------------------------------------------
__device__ __forceinline__ float blockSum512(float v, float* red) {
    const int lane = threadIdx.x & 31, warp = threadIdx.x >> 5;
#pragma unroll
    for (int o = 16; o > 0; o >>= 1) v += __shfl_xor_sync(0xffffffffu, v, o);
    if (lane == 0) red[warp] = v;
    __syncthreads();
    if (threadIdx.x == 0) {
        float s = 0.f;
        for (int i = 0; i < 16; i++) s += red[i];
        red[16] = s;
    }
    __syncthreads();
    float r = red[16];
    __syncthreads();
    return r;
}

__device__ __forceinline__ float dot4(float4 a, float4 b) {
    return a.x * b.x + a.y * b.y + a.z * b.z + a.w * b.w;
}

__global__ void __launch_bounds__(512) frame_kernel(const float* __restrict__ Abox,
                                                    const float* __restrict__ ln_w,
                                                    const float* __restrict__ ln_b,
                                                    float* __restrict__ out,
                                                    float* __restrict__ rg_out) {
    const int f = blockIdx.x;
    const int tid = threadIdx.x;
    const int lane = tid & 31, warp = tid >> 5;

    __shared__ float px[12], py[12], sqs[12];
    __shared__ float s_u[12], s_v[12];
    __shared__ float s_rg[12][12];
    __shared__ float red[17];

    if (tid < 12) {
        const float* bx = Abox + ((size_t)f * 12 + tid) * 4;
        float cx = (bx[0] + bx[2]) * 0.5f;
        float cy = (bx[1] + bx[3]) * 0.5f;
        px[tid] = cx; py[tid] = cy; sqs[tid] = cx * cx + cy * cy;
    }

    if (warp < 12) {
        const float4* frow = (const float4*)(g_feat + ((size_t)f * 12 + warp) * NF_);
        const float4* vt4 = (const float4*)g_vtp;
        const float4* vp4 = (const float4*)g_vpt;
        float ua = 0.f, va = 0.f;
#pragma unroll
        for (int k = 0; k < 8; k++) {
            float4 fv = frow[lane + 32 * k];
            ua += dot4(fv, vt4[lane + 32 * k]);
            va += dot4(fv, vp4[lane + 32 * k]);
        }
#pragma unroll
        for (int o = 16; o > 0; o >>= 1) {
            ua += __shfl_xor_sync(0xffffffffu, ua, o);
            va += __shfl_xor_sync(0xffffffffu, va, o);
        }
        if (lane == 0) { s_u[warp] = ua; s_v[warp] = va; }
    }
    __syncthreads();

    if (warp < 12) {
        const int n = warp;
        const float4* tM4 = (const float4*)(g_TG + ((size_t)f * 12 + n) * NB_);
        float4 tr[8];
#pragma unroll
        for (int k = 0; k < 8; k++) tr[k] = tM4[lane + 32 * k];
        float lg[12];
#pragma unroll
        for (int m = 0; m < 12; m++) {
            const float4* fm4 = (const float4*)(g_feat + ((size_t)f * 12 + m) * NF_);
            float a = 0.f;
#pragma unroll
            for (int k = 0; k < 8; k++) a += dot4(tr[k], fm4[lane + 32 * k]);
#pragma unroll
            for (int o = 16; o > 0; o >>= 1) a += __shfl_xor_sync(0xffffffffu, a, o);
            lg[m] = a;
        }
        if (lane == 0) {
            const float bb = g_bb[0];
            const float scale = 0.03125f;
            float e[12];
            bool msk[12];
            float mx = -INFINITY;
#pragma unroll
            for (int m = 0; m < 12; m++) {
                float d2 = sqs[n] - 2.f * (px[n] * px[m] + py[n] * py[m]) + sqs[m];
                d2 = fmaxf(d2, 0.f);
                float dist = sqrtf(d2);
                msk[m] = (dist > 0.4f);
                float v = (lg[m] + s_u[n] + s_v[m] + bb) * scale;
                e[m] = v;
                if (!msk[m]) mx = fmaxf(mx, v);
            }
            float se = 0.f;
#pragma unroll
            for (int m = 0; m < 12; m++) {
                float ev = msk[m] ? 0.f : expf(e[m] - mx);
                e[m] = ev;
                se += ev;
            }
            float inv = 1.f / se;
#pragma unroll
            for (int m = 0; m < 12; m++) {
                float r = e[m] * inv;
                s_rg[n][m] = r;
                if (rg_out) rg_out[((size_t)f * 12 + n) * 12 + m] = r;
            }
        }
    }
    __syncthreads();

    float2 aggv[12];
    {
        float2 gv[12];
#pragma unroll
        for (int m = 0; m < 12; m++)
            gv[m] = ((const float2*)(g_TG + ((size_t)f * 12 + m) * NB_ + NF_))[tid];
#pragma unroll
        for (int n = 0; n < 12; n++) {
            float ax = 0.f, ay = 0.f;
#pragma unroll
            for (int m = 0; m < 12; m++) {
                float w = s_rg[n][m];
                ax += w * gv[m].x;
                ay += w * gv[m].y;
            }
            aggv[n] = make_float2(ax, ay);
        }
    }
    float lsum = 0.f;
#pragma unroll
    for (int n = 0; n < 12; n++) lsum += aggv[n].x + aggv[n].y;
    const float mu = blockSum512(lsum, red) * (1.f / 12288.f);

    float lsq = 0.f;
#pragma unroll
    for (int n = 0; n < 12; n++) {
        float dx = aggv[n].x - mu, dy = aggv[n].y - mu;
        lsq += dx * dx + dy * dy;
    }
    const float var = blockSum512(lsq, red) * (1.f / 12288.f);
    const float rstd = rsqrtf(var + 1e-5f);

    const float2* lw2 = (const float2*)ln_w;
    const float2* lb2 = (const float2*)ln_b;
    float2* out2 = (float2*)out;
#pragma unroll
    for (int n = 0; n < 12; n++) {
        float2 w = lw2[n * 512 + tid];
        float2 b = lb2[n * 512 + tid];
        float yx = (aggv[n].x - mu) * rstd * w.x + b.x;
        float yy = (aggv[n].y - mu) * rstd * w.y + b.y;
        out2[((size_t)f * 12 + n) * 512 + tid] = make_float2(fmaxf(yx, 0.f), fmaxf(yy, 0.f));
    }
}

// ---------------------------------------------------------------------------
extern "C" void kernel_launch(void* const* d_in, const int* in_sizes, int n_in,
                              void* d_out, int out_size) {
    const float* x  = (const float*)d_in[0];
    const float* A  = (const float*)d_in[1];
    const float* wt = (const float*)d_in[2];
    const float* bt = (const float*)d_in[3];
    const float* wp = (const float*)d_in[4];
    const float* bp = (const float*)d_in[5];
    const float* wg = (const float*)d_in[6];
    const float* lw = (const float*)d_in[7];
    const float* lb = (const float*)d_in[8];

    float* out = (float*)d_out;
    float* rg = (out_size >= (int)(ROWS_ * NF_ + BT_ * N_ * N_))
                    ? out + (size_t)ROWS_ * NF_
                    : nullptr;

    float *feat, *TG, *BigB, *wtr, *wpr;
    cudaGetSymbolAddress((void**)&feat, g_feat);
    cudaGetSymbolAddress((void**)&TG, g_TG);
    cudaGetSymbolAddress((void**)&BigB, g_BigB);
    cudaGetSymbolAddress((void**)&wtr, g_wtr);
    cudaGetSymbolAddress((void**)&wpr, g_wpr);

    const int smem_small = STAGES * (64 * 128 + B_STAGE);    // 73728
    cudaFuncSetAttribute(mma_gemm<64, true>,
                         cudaFuncAttributeMaxDynamicSharedMemorySize, smem_small);
    cudaFuncSetAttribute(mma_gemm_big,
                         cudaFuncAttributeMaxDynamicSharedMemorySize, BIG_SMEM);

    // Launch order: big GEMM is launch #4 (ncu consistently profiles #4)
    prep_w<<<3072, 256>>>(wt, wp, wg);                                       // 1
    transpose_x<<<dim3(TN_ / 128, NF_ / 32, B_), 256>>>(x);                  // 2
    // MwT[n,k] = sum_r wphi[n,r]*wtheta[k,r] -> BigB rows 0..1023 (rounded)
    mma_gemm<64, true><<<dim3(NF_ / BN, NF_ / 64), 256, smem_small>>>(       // 3
        wpr, wtr, BigB, NF_, NF_);
    // [tM | G] = feat @ [MwT | wg^T]^T   (fused, N = 2048)
    mma_gemm_big<<<dim3(NB_ / 128, ROWS_ / 128), 128, BIG_SMEM>>>(           // 4
        feat, BigB, TG);

    bias_vecs<<<128, 256>>>(wt, bt, wp, bp);                                 // 5
    frame_kernel<<<BT_, 512>>>(A, lw, lb, out, rg);                          // 6
}

// round 10
// speedup vs baseline: 1.7806x; 1.6138x over previous
#include <cuda_runtime.h>
#include <cuda_fp16.h>
#include <math.h>
#include <stdint.h>

// Problem constants
#define B_    16
#define C_    1024
#define T_    64
#define N_    12
#define BT_   (B_ * T_)       // 1024 frames
#define NF_   1024
#define ROWS_ (BT_ * N_)      // 12288
#define TN_   (T_ * N_)       // 768
#define NB_   2048            // fused B rows: [MwT | wg^T]

// Scratch (static device globals)
__device__ __half g_feat[ROWS_ * NF_];   // feat, rn-rounded to fp16
__device__ float  g_TG[ROWS_ * NB_];     // [tM | G] fused output (fp32)
__device__ __half g_BigB[NB_ * NF_];     // rows 0-1023: MwT, 1024-2047: wg^T
__device__ __half g_wtr[NF_ * NF_];      // Wtheta rounded to fp16
__device__ __half g_wpr[NF_ * NF_];      // Wphi rounded to fp16
__device__ float  g_vtp[NF_];
__device__ float  g_vpt[NF_];
__device__ float  g_bb[1];

// ---------------------------------------------------------------------------
// Helpers (baseline PTX only)
// ---------------------------------------------------------------------------
__device__ __forceinline__ uint32_t smem_u32(const void* p) {
    uint32_t a;
    asm("{ .reg .u64 t; cvta.to.shared.u64 t, %1; cvt.u32.u64 %0, t; }" : "=r"(a) : "l"(p));
    return a;
}
__device__ __forceinline__ void cp16(uint32_t s, const void* g) {
    asm volatile("cp.async.cg.shared.global [%0], [%1], 16;" :: "r"(s), "l"(g) : "memory");
}
#define CP_COMMIT() asm volatile("cp.async.commit_group;" ::: "memory")
#define SWZ(x) ((x) ^ (((x) >> 3) & 0x70))

__device__ __forceinline__ void ldsm4(uint32_t* r, uint32_t addr) {
    asm volatile("ldmatrix.sync.aligned.m8n8.x4.shared.b16 {%0,%1,%2,%3}, [%4];"
                 : "=r"(r[0]), "=r"(r[1]), "=r"(r[2]), "=r"(r[3]) : "r"(addr));
}
// fp16 MMA, fp32 accumulate: D[16x8] += A[16x16] * B[16x8]
__device__ __forceinline__ void mma_f16(float* c, const uint32_t* a, uint32_t b0, uint32_t b1) {
    asm volatile("mma.sync.aligned.m16n8k16.row.col.f32.f16.f16.f32 "
                 "{%0,%1,%2,%3}, {%4,%5,%6,%7}, {%8,%9}, {%0,%1,%2,%3};"
                 : "+f"(c[0]), "+f"(c[1]), "+f"(c[2]), "+f"(c[3])
                 : "r"(a[0]), "r"(a[1]), "r"(a[2]), "r"(a[3]), "r"(b0), "r"(b1));
}

#define BK 64          // fp16: 64 halves = 128B rows
#define STAGES 3

// ---------------------------------------------------------------------------
// Big GEMM (fp16): 128 thr (4 warps), CTA 128x128, warp 64x64, 3 stages,
// 2 CTA/SM. C[m,n] = sum_k A[m,k]*Bm[n,k]; A half[M,1024], Bm half[N,1024].
// ---------------------------------------------------------------------------
#define BIG_STG 16384
#define BIG_SMEM (STAGES * 2 * BIG_STG)   // 98304

__global__ void __launch_bounds__(128, 2) mma_gemm_big(const __half* __restrict__ A,
                                                       const __half* __restrict__ Bm,
                                                       float* __restrict__ C) {
    const int K = NF_, ldc = NB_;
    extern __shared__ char smem[];
    const uint32_t sb = smem_u32(smem);
    const int tid = threadIdx.x, lane = tid & 31, wid = tid >> 5;
    const int m0 = blockIdx.y * 128, n0 = blockIdx.x * 128;
    const int warp_m = wid & 1, warp_n = wid >> 1;   // 2x2 warps, 64x64 each

    // cp.async tiling: 8 threads x 16B (8 halves) per 128B row, 16 rows/pass
    const int r = tid >> 3;
    const int o16 = (tid & 7) << 4;
    const int c8 = (tid & 7) << 3;

    float acc[4][8][4];
#pragma unroll
    for (int i = 0; i < 4; i++)
#pragma unroll
        for (int j = 0; j < 8; j++)
#pragma unroll
            for (int k = 0; k < 4; k++) acc[i][j][k] = 0.f;

    const int lrow = lane & 15;
    const int lcol = (lane >> 4) << 4;
    uint32_t a_base[4], b_base[4];
#pragma unroll
    for (int mt = 0; mt < 4; mt++)
        a_base[mt] = (uint32_t)((warp_m * 64 + mt * 16 + lrow) * 128 + lcol);
#pragma unroll
    for (int nh = 0; nh < 4; nh++)
        b_base[nh] = (uint32_t)((warp_n * 64 + nh * 16 + lrow) * 128 + lcol);

#define LOAD_STAGE_BIG(chunk, stage)                                               \
    do {                                                                           \
        uint32_t sA = sb + (stage) * BIG_STG;                                      \
        uint32_t sB = sb + STAGES * BIG_STG + (stage) * BIG_STG;                   \
        int k0 = (chunk) * BK;                                                     \
        _Pragma("unroll") for (int t = 0; t < 8; t++) {                            \
            int rr = r + t * 16;                                                   \
            cp16(sA + SWZ((uint32_t)(rr * 128 + o16)),                             \
                 A + (size_t)(m0 + rr) * K + k0 + c8);                             \
        }                                                                          \
        _Pragma("unroll") for (int t = 0; t < 8; t++) {                            \
            int rr = r + t * 16;                                                   \
            cp16(sB + SWZ((uint32_t)(rr * 128 + o16)),                             \
                 Bm + (size_t)(n0 + rr) * K + k0 + c8);                            \
        }                                                                          \
        CP_COMMIT();                                                               \
    } while (0)

    LOAD_STAGE_BIG(0, 0);
    LOAD_STAGE_BIG(1, 1);

    const int nk = K / BK;  // 16
    for (int i = 0; i < nk; i++) {
        const int st = i % STAGES;
        if (i + 2 < nk) {
            asm volatile("cp.async.wait_group 1;" ::: "memory");
            __syncthreads();
            LOAD_STAGE_BIG(i + 2, (i + 2) % STAGES);
        } else {
            asm volatile("cp.async.wait_group 0;" ::: "memory");
            __syncthreads();
        }
        const uint32_t sA = sb + st * BIG_STG;
        const uint32_t sB = sb + STAGES * BIG_STG + st * BIG_STG;
#pragma unroll
        for (int ks = 0; ks < 4; ks++) {     // 4 x k16 per BK=64 chunk
            uint32_t a[4][4], b[4][4];
#pragma unroll
            for (int nh = 0; nh < 4; nh++)
                ldsm4(b[nh], sB + SWZ(b_base[nh] + (uint32_t)(ks * 32)));
#pragma unroll
            for (int mt = 0; mt < 4; mt++)
                ldsm4(a[mt], sA + SWZ(a_base[mt] + (uint32_t)(ks * 32)));
#pragma unroll
            for (int mt = 0; mt < 4; mt++)
#pragma unroll
                for (int nt = 0; nt < 8; nt++)
                    mma_f16(acc[mt][nt], a[mt], b[nt >> 1][nt & 1], b[nt >> 1][(nt & 1) + 2]);
        }
    }
#undef LOAD_STAGE_BIG

    const int mrow = lane >> 2;
    const int mcol = (lane & 3) << 1;
#pragma unroll
    for (int mt = 0; mt < 4; mt++) {
#pragma unroll
        for (int nt = 0; nt < 8; nt++) {
            int row = m0 + warp_m * 64 + mt * 16 + mrow;
            int col = n0 + warp_n * 64 + nt * 8 + mcol;
            *(float2*)&C[(size_t)row * ldc + col] =
                make_float2(acc[mt][nt][0], acc[mt][nt][1]);
            *(float2*)&C[(size_t)(row + 8) * ldc + col] =
                make_float2(acc[mt][nt][2], acc[mt][nt][3]);
        }
    }
}

// ---------------------------------------------------------------------------
// Small GEMM (fp16): MwT[n,k] = sum_r wphi[n,r]*wtheta[k,r].
// CTA 64x128, 8 warps (warp 32x32), 2 CTA/SM, output HALF into g_BigB.
// ---------------------------------------------------------------------------
#define SML_ASTG 8192
#define SML_BSTG 16384
#define SML_SMEM (STAGES * (SML_ASTG + SML_BSTG))   // 73728

__global__ void __launch_bounds__(256, 2) mma_gemm_small(const __half* __restrict__ A,
                                                         const __half* __restrict__ Bm,
                                                         __half* __restrict__ C) {
    const int K = NF_, ldc = NF_;
    extern __shared__ char smem[];
    const uint32_t sb = smem_u32(smem);
    const int tid = threadIdx.x, lane = tid & 31, wid = tid >> 5;
    const int m0 = blockIdx.y * 64, n0 = blockIdx.x * 128;
    const int warp_m = wid & 1, warp_n = wid >> 1;   // 2x4 warps, 32x32 each

    const int r = tid >> 3;
    const int o16 = (tid & 7) << 4;
    const int c8 = (tid & 7) << 3;

    float acc[2][4][4];
#pragma unroll
    for (int i = 0; i < 2; i++)
#pragma unroll
        for (int j = 0; j < 4; j++)
#pragma unroll
            for (int k = 0; k < 4; k++) acc[i][j][k] = 0.f;

    const int lrow = lane & 15;
    const int lcol = (lane >> 4) << 4;
    uint32_t a_base[2], b_base[2];
#pragma unroll
    for (int mt = 0; mt < 2; mt++)
        a_base[mt] = (uint32_t)((warp_m * 32 + mt * 16 + lrow) * 128 + lcol);
#pragma unroll
    for (int nh = 0; nh < 2; nh++)
        b_base[nh] = (uint32_t)((warp_n * 32 + nh * 16 + lrow) * 128 + lcol);

#define LOAD_STAGE_SML(chunk, stage)                                               \
    do {                                                                           \
        uint32_t sA = sb + (stage) * SML_ASTG;                                     \
        uint32_t sB = sb + STAGES * SML_ASTG + (stage) * SML_BSTG;                 \
        int k0 = (chunk) * BK;                                                     \
        _Pragma("unroll") for (int t = 0; t < 2; t++) {                            \
            int rr = r + t * 32;                                                   \
            cp16(sA + SWZ((uint32_t)(rr * 128 + o16)),                             \
                 A + (size_t)(m0 + rr) * K + k0 + c8);                             \
        }                                                                          \
        _Pragma("unroll") for (int t = 0; t < 4; t++) {                            \
            int rr = r + t * 32;                                                   \
            cp16(sB + SWZ((uint32_t)(rr * 128 + o16)),                             \
                 Bm + (size_t)(n0 + rr) * K + k0 + c8);                            \
        }                                                                          \
        CP_COMMIT();                                                               \
    } while (0)

    LOAD_STAGE_SML(0, 0);
    LOAD_STAGE_SML(1, 1);

    const int nk = K / BK;  // 16
    for (int i = 0; i < nk; i++) {
        const int st = i % STAGES;
        if (i + 2 < nk) {
            asm volatile("cp.async.wait_group 1;" ::: "memory");
            __syncthreads();
            LOAD_STAGE_SML(i + 2, (i + 2) % STAGES);
        } else {
            asm volatile("cp.async.wait_group 0;" ::: "memory");
            __syncthreads();
        }
        const uint32_t sA = sb + st * SML_ASTG;
        const uint32_t sB = sb + STAGES * SML_ASTG + st * SML_BSTG;
#pragma unroll
        for (int ks = 0; ks < 4; ks++) {
            uint32_t a[2][4], b[2][4];
#pragma unroll
            for (int nh = 0; nh < 2; nh++)
                ldsm4(b[nh], sB + SWZ(b_base[nh] + (uint32_t)(ks * 32)));
#pragma unroll
            for (int mt = 0; mt < 2; mt++)
                ldsm4(a[mt], sA + SWZ(a_base[mt] + (uint32_t)(ks * 32)));
#pragma unroll
            for (int mt = 0; mt < 2; mt++)
#pragma unroll
                for (int nt = 0; nt < 4; nt++)
                    mma_f16(acc[mt][nt], a[mt], b[nt >> 1][nt & 1], b[nt >> 1][(nt & 1) + 2]);
        }
    }
#undef LOAD_STAGE_SML

    const int mrow = lane >> 2;
    const int mcol = (lane & 3) << 1;
#pragma unroll
    for (int mt = 0; mt < 2; mt++) {
#pragma unroll
        for (int nt = 0; nt < 4; nt++) {
            int row = m0 + warp_m * 32 + mt * 16 + mrow;
            int col = n0 + warp_n * 32 + nt * 8 + mcol;
            __half2 h0 = __floats2half2_rn(acc[mt][nt][0], acc[mt][nt][1]);
            __half2 h1 = __floats2half2_rn(acc[mt][nt][2], acc[mt][nt][3]);
            *(__half2*)&C[(size_t)row * ldc + col] = h0;
            *(__half2*)&C[(size_t)(row + 8) * ldc + col] = h1;
        }
    }
}

// ---------------------------------------------------------------------------
// Fused prep: blocks 0-2047 round wt/wp -> half; 2048-3071 transpose wg -> half
// (into g_BigB rows 1024+); 3072-3199 bias cross-term vectors (fp32 exact).
// ---------------------------------------------------------------------------
__global__ void prep_w(const float* __restrict__ wt, const float* __restrict__ wp,
                       const float* __restrict__ wg,
                       const float* __restrict__ bt, const float* __restrict__ bp) {
    const int bi = blockIdx.x;
    const int tid = threadIdx.x;
    if (bi < 2048) {
        const float4* in = (bi < 1024) ? (const float4*)wt : (const float4*)wp;
        __half* outp = (bi < 1024) ? g_wtr : g_wpr;
        const int i = (bi & 1023) * 256 + tid;
        float4 v = in[i];
        __half2 h01 = __floats2half2_rn(v.x, v.y);
        __half2 h23 = __floats2half2_rn(v.z, v.w);
        uint2 st;
        st.x = *(uint32_t*)&h01;
        st.y = *(uint32_t*)&h23;
        *(uint2*)(outp + (size_t)i * 4) = st;
    } else if (bi < 3072) {
        __shared__ float tile[32][33];
        const int bb = bi - 2048;
        const int k0 = (bb >> 5) * 32;
        const int n0 = (bb & 31) * 32;
        const int tx = tid & 31, ty = tid >> 5;
#pragma unroll
        for (int i = 0; i < 32; i += 8)
            tile[ty + i][tx] = wg[(size_t)(k0 + ty + i) * NF_ + n0 + tx];
        __syncthreads();
        __half* dst = g_BigB + (size_t)NF_ * NF_;
#pragma unroll
        for (int i = 0; i < 32; i += 8)
            dst[(size_t)(n0 + ty + i) * NF_ + k0 + tx] = __float2half_rn(tile[tx][ty + i]);
    } else {
        const int lane = tid & 31, warp = tid >> 5;
        const int c = (bi - 3072) * 8 + warp;
        const float* wtr = wt + (size_t)c * NF_;
        const float* wpr = wp + (size_t)c * NF_;
        float a = 0.f, b2 = 0.f;
#pragma unroll
        for (int i = 0; i < 32; i++) {
            const int k = lane + 32 * i;
            a  += wtr[k] * bp[k];
            b2 += wpr[k] * bt[k];
        }
#pragma unroll
        for (int o = 16; o > 0; o >>= 1) {
            a  += __shfl_xor_sync(0xffffffffu, a, o);
            b2 += __shfl_xor_sync(0xffffffffu, b2, o);
        }
        if (lane == 0) { g_vtp[c] = a; g_vpt[c] = b2; }
        if (bi == 3072 && warp == 0) {
            float s = 0.f;
#pragma unroll
            for (int i = 0; i < 32; i++) {
                const int k = lane + 32 * i;
                s += bt[k] * bp[k];
            }
#pragma unroll
            for (int o = 16; o > 0; o >>= 1) s += __shfl_xor_sync(0xffffffffu, s, o);
            if (lane == 0) g_bb[0] = s;
        }
    }
}

// ---------------------------------------------------------------------------
// Transpose x[B,C,T,N] -> feat[(b*T+t)*N+n, c] as fp16.
// ---------------------------------------------------------------------------
__global__ void __launch_bounds__(256) transpose_x(const float* __restrict__ x) {
    __shared__ float tile[128][33];
    const int b = blockIdx.z;
    const int c0 = blockIdx.y * 32;
    const int tn0 = blockIdx.x * 128;
    const int tid = threadIdx.x;
    const int lane = tid & 31, wid = tid >> 5;

#pragma unroll
    for (int p = 0; p < 4; p++) {
        const int c = wid + p * 8;
        float4 v = *(const float4*)(x + ((size_t)b * C_ + c0 + c) * TN_ + tn0 + lane * 4);
        tile[lane * 4 + 0][c] = v.x;
        tile[lane * 4 + 1][c] = v.y;
        tile[lane * 4 + 2][c] = v.z;
        tile[lane * 4 + 3][c] = v.w;
    }
    __syncthreads();

    const int cc = (lane & 7) * 4;
    const int tnw = wid * 4 + (lane >> 3);
#pragma unroll
    for (int p = 0; p < 4; p++) {
        const int tn = tnw + p * 32;
        __half2 h01 = __floats2half2_rn(tile[tn][cc + 0], tile[tn][cc + 1]);
        __half2 h23 = __floats2half2_rn(tile[tn][cc + 2], tile[tn][cc + 3]);
        uint2 st;
        st.x = *(uint32_t*)&h01;
        st.y = *(uint32_t*)&h23;
        *(uint2*)(g_feat + ((size_t)b * TN_ + tn0 + tn) * NF_ + c0 + cc) = st;
    }
}

// ---------------------------------------------------------------------------
__device__ __forceinline__ float blockSum512(float v, float* red) {
    const int lane = threadIdx.x & 31, warp = threadIdx.x >> 5;
#pragma unroll
    for (int o = 16; o > 0; o >>= 1) v += __shfl_xor_sync(0xffffffffu, v, o);
    if (lane == 0) red[warp] = v;
    __syncthreads();
    if (threadIdx.x == 0) {
        float s = 0.f;
        for (int i = 0; i < 16; i++) s += red[i];
        red[16] = s;
    }
    __syncthreads();
    float r = red[16];
    __syncthreads();
    return r;
}

__device__ __forceinline__ float dot4(float4 a, float4 b) {
    return a.x * b.x + a.y * b.y + a.z * b.z + a.w * b.w;
}

// Per-frame: logits, mask, softmax, agg, LN, ReLU. feat staged in smem (fp32).
__global__ void __launch_bounds__(512) frame_kernel(const float* __restrict__ Abox,
                                                    const float* __restrict__ ln_w,
                                                    const float* __restrict__ ln_b,
                                                    float* __restrict__ out,
                                                    float* __restrict__ rg_out) {
    extern __shared__ float sfm[];   // [12][1024] fp32 feat for this frame
    const int f = blockIdx.x;
    const int tid = threadIdx.x;
    const int lane = tid & 31, warp = tid >> 5;

    __shared__ float px[12], py[12], sqs[12];
    __shared__ float s_u[12], s_v[12];
    __shared__ float s_rg[12][12];
    __shared__ float red[17];

    if (tid < 12) {
        const float* bx = Abox + ((size_t)f * 12 + tid) * 4;
        float cx = (bx[0] + bx[2]) * 0.5f;
        float cy = (bx[1] + bx[3]) * 0.5f;
        px[tid] = cx; py[tid] = cy; sqs[tid] = cx * cx + cy * cy;
    }

    // stage feat_f (12 x 1024 halves) into smem as fp32
    {
        const __half2* src = (const __half2*)(g_feat + (size_t)f * 12 * NF_);
#pragma unroll
        for (int i = 0; i < 12; i++) {
            const int idx = tid + i * 512;       // 6144 half2 total
            float2 v = __half22float2(src[idx]);
            sfm[idx * 2] = v.x;
            sfm[idx * 2 + 1] = v.y;
        }
    }
    __syncthreads();

    // phase 1: bias cross terms from smem feat
    if (warp < 12) {
        const float4* frow = (const float4*)(sfm + warp * NF_);
        const float4* vt4 = (const float4*)g_vtp;
        const float4* vp4 = (const float4*)g_vpt;
        float ua = 0.f, va = 0.f;
#pragma unroll
        for (int k = 0; k < 8; k++) {
            float4 fv = frow[lane + 32 * k];
            ua += dot4(fv, vt4[lane + 32 * k]);
            va += dot4(fv, vp4[lane + 32 * k]);
        }
#pragma unroll
        for (int o = 16; o > 0; o >>= 1) {
            ua += __shfl_xor_sync(0xffffffffu, ua, o);
            va += __shfl_xor_sync(0xffffffffu, va, o);
        }
        if (lane == 0) { s_u[warp] = ua; s_v[warp] = va; }
    }
    __syncthreads();

    // phase 2: logits (tM row from global, fm from smem); mask + softmax
    if (warp < 12) {
        const int n = warp;
        const float4* tM4 = (const float4*)(g_TG + ((size_t)f * 12 + n) * NB_);
        float4 tr[8];
#pragma unroll
        for (int k = 0; k < 8; k++) tr[k] = tM4[lane + 32 * k];
        float lg[12];
#pragma unroll
        for (int m = 0; m < 12; m++) {
            const float4* fm4 = (const float4*)(sfm + m * NF_);
            float a = 0.f;
#pragma unroll
            for (int k = 0; k < 8; k++) a += dot4(tr[k], fm4[lane + 32 * k]);
#pragma unroll
            for (int o = 16; o > 0; o >>= 1) a += __shfl_xor_sync(0xffffffffu, a, o);
            lg[m] = a;
        }
        if (lane == 0) {
            const float bb = g_bb[0];
            const float scale = 0.03125f;
            float e[12];
            bool msk[12];
            float mx = -INFINITY;
#pragma unroll
            for (int m = 0; m < 12; m++) {
                float d2 = sqs[n] - 2.f * (px[n] * px[m] + py[n] * py[m]) + sqs[m];
                d2 = fmaxf(d2, 0.f);
                float dist = sqrtf(d2);
                msk[m] = (dist > 0.4f);
                float v = (lg[m] + s_u[n] + s_v[m] + bb) * scale;
                e[m] = v;
                if (!msk[m]) mx = fmaxf(mx, v);
            }
            float se = 0.f;
#pragma unroll
            for (int m = 0; m < 12; m++) {
                float ev = msk[m] ? 0.f : expf(e[m] - mx);
                e[m] = ev;
                se += ev;
            }
            float inv = 1.f / se;
#pragma unroll
            for (int m = 0; m < 12; m++) {
                float r = e[m] * inv;
                s_rg[n][m] = r;
                if (rg_out) rg_out[((size_t)f * 12 + n) * 12 + m] = r;
            }
        }
    }
    __syncthreads();

    // phase 3: agg = rg @ G_f; LayerNorm + ReLU
    float2 aggv[12];
    {
        float2 gv[12];
#pragma unroll
        for (int m = 0; m < 12; m++)
            gv[m] = ((const float2*)(g_TG + ((size_t)f * 12 + m) * NB_ + NF_))[tid];
#pragma unroll
        for (int n = 0; n < 12; n++) {
            float ax = 0.f, ay = 0.f;
#pragma unroll
            for (int m = 0; m < 12; m++) {
                float w = s_rg[n][m];
                ax += w * gv[m].x;
                ay += w * gv[m].y;
            }
            aggv[n] = make_float2(ax, ay);
        }
    }
    float lsum = 0.f;
#pragma unroll
    for (int n = 0; n < 12; n++) lsum += aggv[n].x + aggv[n].y;
    const float mu = blockSum512(lsum, red) * (1.f / 12288.f);

    float lsq = 0.f;
#pragma unroll
    for (int n = 0; n < 12; n++) {
        float dx = aggv[n].x - mu, dy = aggv[n].y - mu;
        lsq += dx * dx + dy * dy;
    }
    const float var = blockSum512(lsq, red) * (1.f / 12288.f);
    const float rstd = rsqrtf(var + 1e-5f);

    const float2* lw2 = (const float2*)ln_w;
    const float2* lb2 = (const float2*)ln_b;
    float2* out2 = (float2*)out;
#pragma unroll
    for (int n = 0; n < 12; n++) {
        float2 w = lw2[n * 512 + tid];
        float2 b = lb2[n * 512 + tid];
        float yx = (aggv[n].x - mu) * rstd * w.x + b.x;
        float yy = (aggv[n].y - mu) * rstd * w.y + b.y;
        out2[((size_t)f * 12 + n) * 512 + tid] = make_float2(fmaxf(yx, 0.f), fmaxf(yy, 0.f));
    }
}

// ---------------------------------------------------------------------------
extern "C" void kernel_launch(void* const* d_in, const int* in_sizes, int n_in,
                              void* d_out, int out_size) {
    const float* x  = (const float*)d_in[0];
    const float* A  = (const float*)d_in[1];
    const float* wt = (const float*)d_in[2];
    const float* bt = (const float*)d_in[3];
    const float* wp = (const float*)d_in[4];
    const float* bp = (const float*)d_in[5];
    const float* wg = (const float*)d_in[6];
    const float* lw = (const float*)d_in[7];
    const float* lb = (const float*)d_in[8];

    float* out = (float*)d_out;
    float* rg = (out_size >= (int)(ROWS_ * NF_ + BT_ * N_ * N_))
                    ? out + (size_t)ROWS_ * NF_
                    : nullptr;

    __half *feat, *BigB, *wtr, *wpr;
    float *TG;
    cudaGetSymbolAddress((void**)&feat, g_feat);
    cudaGetSymbolAddress((void**)&TG, g_TG);
    cudaGetSymbolAddress((void**)&BigB, g_BigB);
    cudaGetSymbolAddress((void**)&wtr, g_wtr);
    cudaGetSymbolAddress((void**)&wpr, g_wpr);

    cudaFuncSetAttribute(mma_gemm_small,
                         cudaFuncAttributeMaxDynamicSharedMemorySize, SML_SMEM);
    cudaFuncSetAttribute(mma_gemm_big,
                         cudaFuncAttributeMaxDynamicSharedMemorySize, BIG_SMEM);
    cudaFuncSetAttribute(frame_kernel,
                         cudaFuncAttributeMaxDynamicSharedMemorySize, 49152);

    // Launch order: big GEMM is launch #4 (ncu consistently profiles #4)
    prep_w<<<3200, 256>>>(wt, wp, wg, bt, bp);                               // 1
    transpose_x<<<dim3(TN_ / 128, NF_ / 32, B_), 256>>>(x);                  // 2
    // MwT -> BigB rows 0..1023 (half)
    mma_gemm_small<<<dim3(NF_ / 128, NF_ / 64), 256, SML_SMEM>>>(            // 3
        wpr, wtr, BigB);
    // [tM | G] = feat @ [MwT | wg^T]^T   (fused, N = 2048, fp32 out)
    mma_gemm_big<<<dim3(NB_ / 128, ROWS_ / 128), 128, BIG_SMEM>>>(           // 4
        feat, BigB, TG);
    frame_kernel<<<BT_, 512, 49152>>>(A, lw, lb, out, rg);                   // 5
}

// round 11
// speedup vs baseline: 1.8529x; 1.0406x over previous
#include <cuda_runtime.h>
#include <cuda_fp16.h>
#include <math.h>
#include <stdint.h>

// Problem constants
#define B_    16
#define C_    1024
#define T_    64
#define N_    12
#define BT_   (B_ * T_)       // 1024 frames
#define NF_   1024
#define ROWS_ (BT_ * N_)      // 12288
#define TN_   (T_ * N_)       // 768
#define NB_   2048            // fused B rows: [MwT | wg^T]

// Scratch (static device globals)
__device__ __half g_feat[ROWS_ * NF_];   // feat, rn-rounded to fp16
__device__ __half g_TG[ROWS_ * NB_];     // [tM | G] fused output (fp16)
__device__ __half g_BigB[NB_ * NF_];     // rows 0-1023: MwT, 1024-2047: wg^T
__device__ __half g_wtr[NF_ * NF_];      // Wtheta rounded to fp16
__device__ __half g_wpr[NF_ * NF_];      // Wphi rounded to fp16
__device__ float  g_vtp[NF_];
__device__ float  g_vpt[NF_];
__device__ float  g_bb[1];

// ---------------------------------------------------------------------------
// Helpers (baseline PTX only)
// ---------------------------------------------------------------------------
__device__ __forceinline__ uint32_t smem_u32(const void* p) {
    uint32_t a;
    asm("{ .reg .u64 t; cvta.to.shared.u64 t, %1; cvt.u32.u64 %0, t; }" : "=r"(a) : "l"(p));
    return a;
}
__device__ __forceinline__ void cp16(uint32_t s, const void* g) {
    asm volatile("cp.async.cg.shared.global [%0], [%1], 16;" :: "r"(s), "l"(g) : "memory");
}
#define CP_COMMIT() asm volatile("cp.async.commit_group;" ::: "memory")
#define SWZ(x) ((x) ^ (((x) >> 3) & 0x70))

__device__ __forceinline__ void ldsm4(uint32_t* r, uint32_t addr) {
    asm volatile("ldmatrix.sync.aligned.m8n8.x4.shared.b16 {%0,%1,%2,%3}, [%4];"
                 : "=r"(r[0]), "=r"(r[1]), "=r"(r[2]), "=r"(r[3]) : "r"(addr));
}
// fp16 MMA, fp32 accumulate: D[16x8] += A[16x16] * B[16x8]
__device__ __forceinline__ void mma_f16(float* c, const uint32_t* a, uint32_t b0, uint32_t b1) {
    asm volatile("mma.sync.aligned.m16n8k16.row.col.f32.f16.f16.f32 "
                 "{%0,%1,%2,%3}, {%4,%5,%6,%7}, {%8,%9}, {%0,%1,%2,%3};"
                 : "+f"(c[0]), "+f"(c[1]), "+f"(c[2]), "+f"(c[3])
                 : "r"(a[0]), "r"(a[1]), "r"(a[2]), "r"(a[3]), "r"(b0), "r"(b1));
}

#define BK 64          // fp16: 64 halves = 128B rows
#define STAGES 3

// ---------------------------------------------------------------------------
// Big GEMM (fp16): 128 thr (4 warps), CTA 128x128, warp 64x64, 3 stages,
// 2 CTA/SM. C[m,n] = sum_k A[m,k]*Bm[n,k]; half in, HALF out.
// ---------------------------------------------------------------------------
#define BIG_STG 16384
#define BIG_SMEM (STAGES * 2 * BIG_STG)   // 98304

__global__ void __launch_bounds__(128, 2) mma_gemm_big(const __half* __restrict__ A,
                                                       const __half* __restrict__ Bm,
                                                       __half* __restrict__ C) {
    const int K = NF_, ldc = NB_;
    extern __shared__ char smem[];
    const uint32_t sb = smem_u32(smem);
    const int tid = threadIdx.x, lane = tid & 31, wid = tid >> 5;
    const int m0 = blockIdx.y * 128, n0 = blockIdx.x * 128;
    const int warp_m = wid & 1, warp_n = wid >> 1;   // 2x2 warps, 64x64 each

    const int r = tid >> 3;
    const int o16 = (tid & 7) << 4;
    const int c8 = (tid & 7) << 3;

    float acc[4][8][4];
#pragma unroll
    for (int i = 0; i < 4; i++)
#pragma unroll
        for (int j = 0; j < 8; j++)
#pragma unroll
            for (int k = 0; k < 4; k++) acc[i][j][k] = 0.f;

    const int lrow = lane & 15;
    const int lcol = (lane >> 4) << 4;
    uint32_t a_base[4], b_base[4];
#pragma unroll
    for (int mt = 0; mt < 4; mt++)
        a_base[mt] = (uint32_t)((warp_m * 64 + mt * 16 + lrow) * 128 + lcol);
#pragma unroll
    for (int nh = 0; nh < 4; nh++)
        b_base[nh] = (uint32_t)((warp_n * 64 + nh * 16 + lrow) * 128 + lcol);

#define LOAD_STAGE_BIG(chunk, stage)                                               \
    do {                                                                           \
        uint32_t sA = sb + (stage) * BIG_STG;                                      \
        uint32_t sB = sb + STAGES * BIG_STG + (stage) * BIG_STG;                   \
        int k0 = (chunk) * BK;                                                     \
        _Pragma("unroll") for (int t = 0; t < 8; t++) {                            \
            int rr = r + t * 16;                                                   \
            cp16(sA + SWZ((uint32_t)(rr * 128 + o16)),                             \
                 A + (size_t)(m0 + rr) * K + k0 + c8);                             \
        }                                                                          \
        _Pragma("unroll") for (int t = 0; t < 8; t++) {                            \
            int rr = r + t * 16;                                                   \
            cp16(sB + SWZ((uint32_t)(rr * 128 + o16)),                             \
                 Bm + (size_t)(n0 + rr) * K + k0 + c8);                            \
        }                                                                          \
        CP_COMMIT();                                                               \
    } while (0)

    LOAD_STAGE_BIG(0, 0);
    LOAD_STAGE_BIG(1, 1);

    const int nk = K / BK;  // 16
    for (int i = 0; i < nk; i++) {
        const int st = i % STAGES;
        if (i + 2 < nk) {
            asm volatile("cp.async.wait_group 1;" ::: "memory");
            __syncthreads();
            LOAD_STAGE_BIG(i + 2, (i + 2) % STAGES);
        } else {
            asm volatile("cp.async.wait_group 0;" ::: "memory");
            __syncthreads();
        }
        const uint32_t sA = sb + st * BIG_STG;
        const uint32_t sB = sb + STAGES * BIG_STG + st * BIG_STG;
#pragma unroll
        for (int ks = 0; ks < 4; ks++) {     // 4 x k16 per BK=64 chunk
            uint32_t a[4][4], b[4][4];
#pragma unroll
            for (int nh = 0; nh < 4; nh++)
                ldsm4(b[nh], sB + SWZ(b_base[nh] + (uint32_t)(ks * 32)));
#pragma unroll
            for (int mt = 0; mt < 4; mt++)
                ldsm4(a[mt], sA + SWZ(a_base[mt] + (uint32_t)(ks * 32)));
#pragma unroll
            for (int mt = 0; mt < 4; mt++)
#pragma unroll
                for (int nt = 0; nt < 8; nt++)
                    mma_f16(acc[mt][nt], a[mt], b[nt >> 1][nt & 1], b[nt >> 1][(nt & 1) + 2]);
        }
    }
#undef LOAD_STAGE_BIG

    // Epilogue: fp16 stores (half2)
    const int mrow = lane >> 2;
    const int mcol = (lane & 3) << 1;
#pragma unroll
    for (int mt = 0; mt < 4; mt++) {
#pragma unroll
        for (int nt = 0; nt < 8; nt++) {
            int row = m0 + warp_m * 64 + mt * 16 + mrow;
            int col = n0 + warp_n * 64 + nt * 8 + mcol;
            *(__half2*)&C[(size_t)row * ldc + col] =
                __floats2half2_rn(acc[mt][nt][0], acc[mt][nt][1]);
            *(__half2*)&C[(size_t)(row + 8) * ldc + col] =
                __floats2half2_rn(acc[mt][nt][2], acc[mt][nt][3]);
        }
    }
}

// ---------------------------------------------------------------------------
// Small GEMM (fp16): MwT[n,k] = sum_r wphi[n,r]*wtheta[k,r].
// CTA 64x128, 8 warps (warp 32x32), 2 CTA/SM, output HALF into g_BigB.
// ---------------------------------------------------------------------------
#define SML_ASTG 8192
#define SML_BSTG 16384
#define SML_SMEM (STAGES * (SML_ASTG + SML_BSTG))   // 73728

__global__ void __launch_bounds__(256, 2) mma_gemm_small(const __half* __restrict__ A,
                                                         const __half* __restrict__ Bm,
                                                         __half* __restrict__ C) {
    const int K = NF_, ldc = NF_;
    extern __shared__ char smem[];
    const uint32_t sb = smem_u32(smem);
    const int tid = threadIdx.x, lane = tid & 31, wid = tid >> 5;
    const int m0 = blockIdx.y * 64, n0 = blockIdx.x * 128;
    const int warp_m = wid & 1, warp_n = wid >> 1;   // 2x4 warps, 32x32 each

    const int r = tid >> 3;
    const int o16 = (tid & 7) << 4;
    const int c8 = (tid & 7) << 3;

    float acc[2][4][4];
#pragma unroll
    for (int i = 0; i < 2; i++)
#pragma unroll
        for (int j = 0; j < 4; j++)
#pragma unroll
            for (int k = 0; k < 4; k++) acc[i][j][k] = 0.f;

    const int lrow = lane & 15;
    const int lcol = (lane >> 4) << 4;
    uint32_t a_base[2], b_base[2];
#pragma unroll
    for (int mt = 0; mt < 2; mt++)
        a_base[mt] = (uint32_t)((warp_m * 32 + mt * 16 + lrow) * 128 + lcol);
#pragma unroll
    for (int nh = 0; nh < 2; nh++)
        b_base[nh] = (uint32_t)((warp_n * 32 + nh * 16 + lrow) * 128 + lcol);

#define LOAD_STAGE_SML(chunk, stage)                                               \
    do {                                                                           \
        uint32_t sA = sb + (stage) * SML_ASTG;                                     \
        uint32_t sB = sb + STAGES * SML_ASTG + (stage) * SML_BSTG;                 \
        int k0 = (chunk) * BK;                                                     \
        _Pragma("unroll") for (int t = 0; t < 2; t++) {                            \
            int rr = r + t * 32;                                                   \
            cp16(sA + SWZ((uint32_t)(rr * 128 + o16)),                             \
                 A + (size_t)(m0 + rr) * K + k0 + c8);                             \
        }                                                                          \
        _Pragma("unroll") for (int t = 0; t < 4; t++) {                            \
            int rr = r + t * 32;                                                   \
            cp16(sB + SWZ((uint32_t)(rr * 128 + o16)),                             \
                 Bm + (size_t)(n0 + rr) * K + k0 + c8);                            \
        }                                                                          \
        CP_COMMIT();                                                               \
    } while (0)

    LOAD_STAGE_SML(0, 0);
    LOAD_STAGE_SML(1, 1);

    const int nk = K / BK;  // 16
    for (int i = 0; i < nk; i++) {
        const int st = i % STAGES;
        if (i + 2 < nk) {
            asm volatile("cp.async.wait_group 1;" ::: "memory");
            __syncthreads();
            LOAD_STAGE_SML(i + 2, (i + 2) % STAGES);
        } else {
            asm volatile("cp.async.wait_group 0;" ::: "memory");
            __syncthreads();
        }
        const uint32_t sA = sb + st * SML_ASTG;
        const uint32_t sB = sb + STAGES * SML_ASTG + st * SML_BSTG;
#pragma unroll
        for (int ks = 0; ks < 4; ks++) {
            uint32_t a[2][4], b[2][4];
#pragma unroll
            for (int nh = 0; nh < 2; nh++)
                ldsm4(b[nh], sB + SWZ(b_base[nh] + (uint32_t)(ks * 32)));
#pragma unroll
            for (int mt = 0; mt < 2; mt++)
                ldsm4(a[mt], sA + SWZ(a_base[mt] + (uint32_t)(ks * 32)));
#pragma unroll
            for (int mt = 0; mt < 2; mt++)
#pragma unroll
                for (int nt = 0; nt < 4; nt++)
                    mma_f16(acc[mt][nt], a[mt], b[nt >> 1][nt & 1], b[nt >> 1][(nt & 1) + 2]);
        }
    }
#undef LOAD_STAGE_SML

    const int mrow = lane >> 2;
    const int mcol = (lane & 3) << 1;
#pragma unroll
    for (int mt = 0; mt < 2; mt++) {
#pragma unroll
        for (int nt = 0; nt < 4; nt++) {
            int row = m0 + warp_m * 32 + mt * 16 + mrow;
            int col = n0 + warp_n * 32 + nt * 8 + mcol;
            *(__half2*)&C[(size_t)row * ldc + col] =
                __floats2half2_rn(acc[mt][nt][0], acc[mt][nt][1]);
            *(__half2*)&C[(size_t)(row + 8) * ldc + col] =
                __floats2half2_rn(acc[mt][nt][2], acc[mt][nt][3]);
        }
    }
}

// ---------------------------------------------------------------------------
// Fused prep: blocks 0-2047 round wt/wp -> half; 2048-3071 transpose wg -> half
// (into g_BigB rows 1024+); 3072-3199 bias cross-term vectors (fp32 exact).
// ---------------------------------------------------------------------------
__global__ void prep_w(const float* __restrict__ wt, const float* __restrict__ wp,
                       const float* __restrict__ wg,
                       const float* __restrict__ bt, const float* __restrict__ bp) {
    const int bi = blockIdx.x;
    const int tid = threadIdx.x;
    if (bi < 2048) {
        const float4* in = (bi < 1024) ? (const float4*)wt : (const float4*)wp;
        __half* outp = (bi < 1024) ? g_wtr : g_wpr;
        const int i = (bi & 1023) * 256 + tid;
        float4 v = in[i];
        __half2 h01 = __floats2half2_rn(v.x, v.y);
        __half2 h23 = __floats2half2_rn(v.z, v.w);
        uint2 st;
        st.x = *(uint32_t*)&h01;
        st.y = *(uint32_t*)&h23;
        *(uint2*)(outp + (size_t)i * 4) = st;
    } else if (bi < 3072) {
        __shared__ float tile[32][33];
        const int bb = bi - 2048;
        const int k0 = (bb >> 5) * 32;
        const int n0 = (bb & 31) * 32;
        const int tx = tid & 31, ty = tid >> 5;
#pragma unroll
        for (int i = 0; i < 32; i += 8)
            tile[ty + i][tx] = wg[(size_t)(k0 + ty + i) * NF_ + n0 + tx];
        __syncthreads();
        __half* dst = g_BigB + (size_t)NF_ * NF_;
#pragma unroll
        for (int i = 0; i < 32; i += 8)
            dst[(size_t)(n0 + ty + i) * NF_ + k0 + tx] = __float2half_rn(tile[tx][ty + i]);
    } else {
        const int lane = tid & 31, warp = tid >> 5;
        const int c = (bi - 3072) * 8 + warp;
        const float* wtr = wt + (size_t)c * NF_;
        const float* wpr = wp + (size_t)c * NF_;
        float a = 0.f, b2 = 0.f;
#pragma unroll
        for (int i = 0; i < 32; i++) {
            const int k = lane + 32 * i;
            a  += wtr[k] * bp[k];
            b2 += wpr[k] * bt[k];
        }
#pragma unroll
        for (int o = 16; o > 0; o >>= 1) {
            a  += __shfl_xor_sync(0xffffffffu, a, o);
            b2 += __shfl_xor_sync(0xffffffffu, b2, o);
        }
        if (lane == 0) { g_vtp[c] = a; g_vpt[c] = b2; }
        if (bi == 3072 && warp == 0) {
            float s = 0.f;
#pragma unroll
            for (int i = 0; i < 32; i++) {
                const int k = lane + 32 * i;
                s += bt[k] * bp[k];
            }
#pragma unroll
            for (int o = 16; o > 0; o >>= 1) s += __shfl_xor_sync(0xffffffffu, s, o);
            if (lane == 0) g_bb[0] = s;
        }
    }
}

// ---------------------------------------------------------------------------
// Transpose x[B,C,T,N] -> feat[(b*T+t)*N+n, c] as fp16.
// ---------------------------------------------------------------------------
__global__ void __launch_bounds__(256) transpose_x(const float* __restrict__ x) {
    __shared__ float tile[128][33];
    const int b = blockIdx.z;
    const int c0 = blockIdx.y * 32;
    const int tn0 = blockIdx.x * 128;
    const int tid = threadIdx.x;
    const int lane = tid & 31, wid = tid >> 5;

#pragma unroll
    for (int p = 0; p < 4; p++) {
        const int c = wid + p * 8;
        float4 v = *(const float4*)(x + ((size_t)b * C_ + c0 + c) * TN_ + tn0 + lane * 4);
        tile[lane * 4 + 0][c] = v.x;
        tile[lane * 4 + 1][c] = v.y;
        tile[lane * 4 + 2][c] = v.z;
        tile[lane * 4 + 3][c] = v.w;
    }
    __syncthreads();

    const int cc = (lane & 7) * 4;
    const int tnw = wid * 4 + (lane >> 3);
#pragma unroll
    for (int p = 0; p < 4; p++) {
        const int tn = tnw + p * 32;
        __half2 h01 = __floats2half2_rn(tile[tn][cc + 0], tile[tn][cc + 1]);
        __half2 h23 = __floats2half2_rn(tile[tn][cc + 2], tile[tn][cc + 3]);
        uint2 st;
        st.x = *(uint32_t*)&h01;
        st.y = *(uint32_t*)&h23;
        *(uint2*)(g_feat + ((size_t)b * TN_ + tn0 + tn) * NF_ + c0 + cc) = st;
    }
}

// ---------------------------------------------------------------------------
__device__ __forceinline__ float blockSum512(float v, float* red) {
    const int lane = threadIdx.x & 31, warp = threadIdx.x >> 5;
#pragma unroll
    for (int o = 16; o > 0; o >>= 1) v += __shfl_xor_sync(0xffffffffu, v, o);
    if (lane == 0) red[warp] = v;
    __syncthreads();
    if (threadIdx.x == 0) {
        float s = 0.f;
        for (int i = 0; i < 16; i++) s += red[i];
        red[16] = s;
    }
    __syncthreads();
    float r = red[16];
    __syncthreads();
    return r;
}

__device__ __forceinline__ float dot4(float4 a, float4 b) {
    return a.x * b.x + a.y * b.y + a.z * b.z + a.w * b.w;
}

// Per-frame: logits, mask, softmax, agg, LN, ReLU. feat staged in smem (fp32).
__global__ void __launch_bounds__(512) frame_kernel(const float* __restrict__ Abox,
                                                    const float* __restrict__ ln_w,
                                                    const float* __restrict__ ln_b,
                                                    float* __restrict__ out,
                                                    float* __restrict__ rg_out) {
    extern __shared__ float sfm[];   // [12][1024] fp32 feat for this frame
    const int f = blockIdx.x;
    const int tid = threadIdx.x;
    const int lane = tid & 31, warp = tid >> 5;

    __shared__ float px[12], py[12], sqs[12];
    __shared__ float s_u[12], s_v[12];
    __shared__ float s_rg[12][12];
    __shared__ float red[17];

    if (tid < 12) {
        const float* bx = Abox + ((size_t)f * 12 + tid) * 4;
        float cx = (bx[0] + bx[2]) * 0.5f;
        float cy = (bx[1] + bx[3]) * 0.5f;
        px[tid] = cx; py[tid] = cy; sqs[tid] = cx * cx + cy * cy;
    }

    // stage feat_f (12 x 1024 halves) into smem as fp32
    {
        const __half2* src = (const __half2*)(g_feat + (size_t)f * 12 * NF_);
#pragma unroll
        for (int i = 0; i < 12; i++) {
            const int idx = tid + i * 512;       // 6144 half2 total
            float2 v = __half22float2(src[idx]);
            sfm[idx * 2] = v.x;
            sfm[idx * 2 + 1] = v.y;
        }
    }
    __syncthreads();

    // phase 1: bias cross terms from smem feat
    if (warp < 12) {
        const float4* frow = (const float4*)(sfm + warp * NF_);
        const float4* vt4 = (const float4*)g_vtp;
        const float4* vp4 = (const float4*)g_vpt;
        float ua = 0.f, va = 0.f;
#pragma unroll
        for (int k = 0; k < 8; k++) {
            float4 fv = frow[lane + 32 * k];
            ua += dot4(fv, vt4[lane + 32 * k]);
            va += dot4(fv, vp4[lane + 32 * k]);
        }
#pragma unroll
        for (int o = 16; o > 0; o >>= 1) {
            ua += __shfl_xor_sync(0xffffffffu, ua, o);
            va += __shfl_xor_sync(0xffffffffu, va, o);
        }
        if (lane == 0) { s_u[warp] = ua; s_v[warp] = va; }
    }
    __syncthreads();

    // phase 2: logits (tM half rows from global, fm from smem); mask + softmax
    if (warp < 12) {
        const int n = warp;
        const uint2* tM2 = (const uint2*)(g_TG + ((size_t)f * 12 + n) * NB_);
        float4 tr[8];
#pragma unroll
        for (int k = 0; k < 8; k++) {
            uint2 u = tM2[lane + 32 * k];
            float2 f0 = __half22float2(*(__half2*)&u.x);
            float2 f1 = __half22float2(*(__half2*)&u.y);
            tr[k] = make_float4(f0.x, f0.y, f1.x, f1.y);
        }
        float lg[12];
#pragma unroll
        for (int m = 0; m < 12; m++) {
            const float4* fm4 = (const float4*)(sfm + m * NF_);
            float a = 0.f;
#pragma unroll
            for (int k = 0; k < 8; k++) a += dot4(tr[k], fm4[lane + 32 * k]);
#pragma unroll
            for (int o = 16; o > 0; o >>= 1) a += __shfl_xor_sync(0xffffffffu, a, o);
            lg[m] = a;
        }
        if (lane == 0) {
            const float bb = g_bb[0];
            const float scale = 0.03125f;
            float e[12];
            bool msk[12];
            float mx = -INFINITY;
#pragma unroll
            for (int m = 0; m < 12; m++) {
                float d2 = sqs[n] - 2.f * (px[n] * px[m] + py[n] * py[m]) + sqs[m];
                d2 = fmaxf(d2, 0.f);
                float dist = sqrtf(d2);
                msk[m] = (dist > 0.4f);
                float v = (lg[m] + s_u[n] + s_v[m] + bb) * scale;
                e[m] = v;
                if (!msk[m]) mx = fmaxf(mx, v);
            }
            float se = 0.f;
#pragma unroll
            for (int m = 0; m < 12; m++) {
                float ev = msk[m] ? 0.f : expf(e[m] - mx);
                e[m] = ev;
                se += ev;
            }
            float inv = 1.f / se;
#pragma unroll
            for (int m = 0; m < 12; m++) {
                float r = e[m] * inv;
                s_rg[n][m] = r;
                if (rg_out) rg_out[((size_t)f * 12 + n) * 12 + m] = r;
            }
        }
    }
    __syncthreads();

    // phase 3: agg = rg @ G_f (G half2); LayerNorm + ReLU
    float2 aggv[12];
    {
        float2 gv[12];
#pragma unroll
        for (int m = 0; m < 12; m++) {
            const __half2* g2 = (const __half2*)(g_TG + ((size_t)f * 12 + m) * NB_ + NF_);
            gv[m] = __half22float2(g2[tid]);
        }
#pragma unroll
        for (int n = 0; n < 12; n++) {
            float ax = 0.f, ay = 0.f;
#pragma unroll
            for (int m = 0; m < 12; m++) {
                float w = s_rg[n][m];
                ax += w * gv[m].x;
                ay += w * gv[m].y;
            }
            aggv[n] = make_float2(ax, ay);
        }
    }
    float lsum = 0.f;
#pragma unroll
    for (int n = 0; n < 12; n++) lsum += aggv[n].x + aggv[n].y;
    const float mu = blockSum512(lsum, red) * (1.f / 12288.f);

    float lsq = 0.f;
#pragma unroll
    for (int n = 0; n < 12; n++) {
        float dx = aggv[n].x - mu, dy = aggv[n].y - mu;
        lsq += dx * dx + dy * dy;
    }
    const float var = blockSum512(lsq, red) * (1.f / 12288.f);
    const float rstd = rsqrtf(var + 1e-5f);

    const float2* lw2 = (const float2*)ln_w;
    const float2* lb2 = (const float2*)ln_b;
    float2* out2 = (float2*)out;
#pragma unroll
    for (int n = 0; n < 12; n++) {
        float2 w = lw2[n * 512 + tid];
        float2 b = lb2[n * 512 + tid];
        float yx = (aggv[n].x - mu) * rstd * w.x + b.x;
        float yy = (aggv[n].y - mu) * rstd * w.y + b.y;
        out2[((size_t)f * 12 + n) * 512 + tid] = make_float2(fmaxf(yx, 0.f), fmaxf(yy, 0.f));
    }
}

// ---------------------------------------------------------------------------
extern "C" void kernel_launch(void* const* d_in, const int* in_sizes, int n_in,
                              void* d_out, int out_size) {
    const float* x  = (const float*)d_in[0];
    const float* A  = (const float*)d_in[1];
    const float* wt = (const float*)d_in[2];
    const float* bt = (const float*)d_in[3];
    const float* wp = (const float*)d_in[4];
    const float* bp = (const float*)d_in[5];
    const float* wg = (const float*)d_in[6];
    const float* lw = (const float*)d_in[7];
    const float* lb = (const float*)d_in[8];

    float* out = (float*)d_out;
    float* rg = (out_size >= (int)(ROWS_ * NF_ + BT_ * N_ * N_))
                    ? out + (size_t)ROWS_ * NF_
                    : nullptr;

    __half *feat, *TG, *BigB, *wtr, *wpr;
    cudaGetSymbolAddress((void**)&feat, g_feat);
    cudaGetSymbolAddress((void**)&TG, g_TG);
    cudaGetSymbolAddress((void**)&BigB, g_BigB);
    cudaGetSymbolAddress((void**)&wtr, g_wtr);
    cudaGetSymbolAddress((void**)&wpr, g_wpr);

    cudaFuncSetAttribute(mma_gemm_small,
                         cudaFuncAttributeMaxDynamicSharedMemorySize, SML_SMEM);
    cudaFuncSetAttribute(mma_gemm_big,
                         cudaFuncAttributeMaxDynamicSharedMemorySize, BIG_SMEM);
    cudaFuncSetAttribute(frame_kernel,
                         cudaFuncAttributeMaxDynamicSharedMemorySize, 49152);

    // Launch order: big GEMM is launch #4 (ncu consistently profiles #4)
    prep_w<<<3200, 256>>>(wt, wp, wg, bt, bp);                               // 1
    transpose_x<<<dim3(TN_ / 128, NF_ / 32, B_), 256>>>(x);                  // 2
    // MwT -> BigB rows 0..1023 (half)
    mma_gemm_small<<<dim3(NF_ / 128, NF_ / 64), 256, SML_SMEM>>>(            // 3
        wpr, wtr, BigB);
    // [tM | G] = feat @ [MwT | wg^T]^T   (fused, N = 2048, fp16 out)
    mma_gemm_big<<<dim3(NB_ / 128, ROWS_ / 128), 128, BIG_SMEM>>>(           // 4
        feat, BigB, TG);
    frame_kernel<<<BT_, 512, 49152>>>(A, lw, lb, out, rg);                   // 5
}

// round 12
// speedup vs baseline: 1.8883x; 1.0191x over previous
#include <cuda_runtime.h>
#include <cuda_fp16.h>
#include <math.h>
#include <stdint.h>

// Problem constants
#define B_    16
#define C_    1024
#define T_    64
#define N_    12
#define BT_   (B_ * T_)       // 1024 frames
#define NF_   1024
#define ROWS_ (BT_ * N_)      // 12288
#define TN_   (T_ * N_)       // 768
#define NB_   2048            // fused B rows: [MwT | wg^T]

// Scratch (static device globals)
__device__ __half g_feat[ROWS_ * NF_];   // feat, rn-rounded to fp16
__device__ __half g_TG[ROWS_ * NB_];     // [tM | G] fused output (fp16)
__device__ __half g_BigB[NB_ * NF_];     // rows 0-1023: MwT, 1024-2047: wg^T
__device__ __half g_wtr[NF_ * NF_];      // Wtheta rounded to fp16
__device__ __half g_wpr[NF_ * NF_];      // Wphi rounded to fp16
__device__ float  g_vtp[NF_];
__device__ float  g_vpt[NF_];
__device__ float  g_bb[1];

// ---------------------------------------------------------------------------
// Helpers (baseline PTX only)
// ---------------------------------------------------------------------------
__device__ __forceinline__ uint32_t smem_u32(const void* p) {
    uint32_t a;
    asm("{ .reg .u64 t; cvta.to.shared.u64 t, %1; cvt.u32.u64 %0, t; }" : "=r"(a) : "l"(p));
    return a;
}
__device__ __forceinline__ void cp16(uint32_t s, const void* g) {
    asm volatile("cp.async.cg.shared.global [%0], [%1], 16;" :: "r"(s), "l"(g) : "memory");
}
#define CP_COMMIT() asm volatile("cp.async.commit_group;" ::: "memory")
#define SWZ(x) ((x) ^ (((x) >> 3) & 0x70))

__device__ __forceinline__ void ldsm4(uint32_t* r, uint32_t addr) {
    asm volatile("ldmatrix.sync.aligned.m8n8.x4.shared.b16 {%0,%1,%2,%3}, [%4];"
                 : "=r"(r[0]), "=r"(r[1]), "=r"(r[2]), "=r"(r[3]) : "r"(addr));
}
// fp16 MMA, fp32 accumulate
__device__ __forceinline__ void mma_f16(float* c, const uint32_t* a, uint32_t b0, uint32_t b1) {
    asm volatile("mma.sync.aligned.m16n8k16.row.col.f32.f16.f16.f32 "
                 "{%0,%1,%2,%3}, {%4,%5,%6,%7}, {%8,%9}, {%0,%1,%2,%3};"
                 : "+f"(c[0]), "+f"(c[1]), "+f"(c[2]), "+f"(c[3])
                 : "r"(a[0]), "r"(a[1]), "r"(a[2]), "r"(a[3]), "r"(b0), "r"(b1));
}

#define BK 64          // fp16: 64 halves = 128B rows
#define STAGES 3

// ---------------------------------------------------------------------------
// Big GEMM (fp16): 128 thr (4 warps), CTA 128x128, warp 64x64, 3 stages,
// 2 CTA/SM. C[m,n] = sum_k A[m,k]*Bm[n,k]; half in, half out.
// ---------------------------------------------------------------------------
#define BIG_STG 16384
#define BIG_SMEM (STAGES * 2 * BIG_STG)   // 98304

__global__ void __launch_bounds__(128, 2) mma_gemm_big(const __half* __restrict__ A,
                                                       const __half* __restrict__ Bm,
                                                       __half* __restrict__ C) {
    const int K = NF_, ldc = NB_;
    extern __shared__ char smem[];
    const uint32_t sb = smem_u32(smem);
    const int tid = threadIdx.x, lane = tid & 31, wid = tid >> 5;
    const int m0 = blockIdx.y * 128, n0 = blockIdx.x * 128;
    const int warp_m = wid & 1, warp_n = wid >> 1;   // 2x2 warps, 64x64 each

    const int r = tid >> 3;
    const int o16 = (tid & 7) << 4;
    const int c8 = (tid & 7) << 3;

    float acc[4][8][4];
#pragma unroll
    for (int i = 0; i < 4; i++)
#pragma unroll
        for (int j = 0; j < 8; j++)
#pragma unroll
            for (int k = 0; k < 4; k++) acc[i][j][k] = 0.f;

    const int lrow = lane & 15;
    const int lcol = (lane >> 4) << 4;
    uint32_t a_base[4], b_base[4];
#pragma unroll
    for (int mt = 0; mt < 4; mt++)
        a_base[mt] = (uint32_t)((warp_m * 64 + mt * 16 + lrow) * 128 + lcol);
#pragma unroll
    for (int nh = 0; nh < 4; nh++)
        b_base[nh] = (uint32_t)((warp_n * 64 + nh * 16 + lrow) * 128 + lcol);

#define LOAD_STAGE_BIG(chunk, stage)                                               \
    do {                                                                           \
        uint32_t sA = sb + (stage) * BIG_STG;                                      \
        uint32_t sB = sb + STAGES * BIG_STG + (stage) * BIG_STG;                   \
        int k0 = (chunk) * BK;                                                     \
        _Pragma("unroll") for (int t = 0; t < 8; t++) {                            \
            int rr = r + t * 16;                                                   \
            cp16(sA + SWZ((uint32_t)(rr * 128 + o16)),                             \
                 A + (size_t)(m0 + rr) * K + k0 + c8);                             \
        }                                                                          \
        _Pragma("unroll") for (int t = 0; t < 8; t++) {                            \
            int rr = r + t * 16;                                                   \
            cp16(sB + SWZ((uint32_t)(rr * 128 + o16)),                             \
                 Bm + (size_t)(n0 + rr) * K + k0 + c8);                            \
        }                                                                          \
        CP_COMMIT();                                                               \
    } while (0)

    LOAD_STAGE_BIG(0, 0);
    LOAD_STAGE_BIG(1, 1);

    const int nk = K / BK;  // 16
    for (int i = 0; i < nk; i++) {
        const int st = i % STAGES;
        if (i + 2 < nk) {
            asm volatile("cp.async.wait_group 1;" ::: "memory");
            __syncthreads();
            LOAD_STAGE_BIG(i + 2, (i + 2) % STAGES);
        } else {
            asm volatile("cp.async.wait_group 0;" ::: "memory");
            __syncthreads();
        }
        const uint32_t sA = sb + st * BIG_STG;
        const uint32_t sB = sb + STAGES * BIG_STG + st * BIG_STG;
#pragma unroll
        for (int ks = 0; ks < 4; ks++) {     // 4 x k16 per BK=64 chunk
            uint32_t a[4][4], b[4][4];
#pragma unroll
            for (int nh = 0; nh < 4; nh++)
                ldsm4(b[nh], sB + SWZ(b_base[nh] + (uint32_t)(ks * 32)));
#pragma unroll
            for (int mt = 0; mt < 4; mt++)
                ldsm4(a[mt], sA + SWZ(a_base[mt] + (uint32_t)(ks * 32)));
#pragma unroll
            for (int mt = 0; mt < 4; mt++)
#pragma unroll
                for (int nt = 0; nt < 8; nt++)
                    mma_f16(acc[mt][nt], a[mt], b[nt >> 1][nt & 1], b[nt >> 1][(nt & 1) + 2]);
        }
    }
#undef LOAD_STAGE_BIG

    const int mrow = lane >> 2;
    const int mcol = (lane & 3) << 1;
#pragma unroll
    for (int mt = 0; mt < 4; mt++) {
#pragma unroll
        for (int nt = 0; nt < 8; nt++) {
            int row = m0 + warp_m * 64 + mt * 16 + mrow;
            int col = n0 + warp_n * 64 + nt * 8 + mcol;
            *(__half2*)&C[(size_t)row * ldc + col] =
                __floats2half2_rn(acc[mt][nt][0], acc[mt][nt][1]);
            *(__half2*)&C[(size_t)(row + 8) * ldc + col] =
                __floats2half2_rn(acc[mt][nt][2], acc[mt][nt][3]);
        }
    }
}

// ---------------------------------------------------------------------------
// FUSED: small GEMM (blocks 0..127) + transpose_x (blocks 128..3199).
// Small: MwT[n,k] = sum_r wphi[n,r]*wtheta[k,r], CTA 64x128, 8 warps, half out.
// Transpose: x[B,C,T,N] -> g_feat[(b*T+t)*N+n, c] as fp16.
// Both 256 threads; dynamic smem = SML_SMEM (transpose uses a prefix).
// ---------------------------------------------------------------------------
#define SML_ASTG 8192
#define SML_BSTG 16384
#define SML_SMEM (STAGES * (SML_ASTG + SML_BSTG))   // 73728
#define SML_BLOCKS 128                               // dim3(8,16) flattened
#define TX_BLOCKS (6 * 32 * 16)                      // 3072

__global__ void __launch_bounds__(256) fused_sg_tx(const __half* __restrict__ Asg,
                                                   const __half* __restrict__ Bsg,
                                                   __half* __restrict__ Csg,
                                                   const float* __restrict__ x) {
    extern __shared__ char smem[];
    const int tid = threadIdx.x;

    if (blockIdx.x < SML_BLOCKS) {
        // ---- small GEMM branch ----
        const int K = NF_, ldc = NF_;
        const uint32_t sb = smem_u32(smem);
        const int lane = tid & 31, wid = tid >> 5;
        const int bx = blockIdx.x & 7, by = blockIdx.x >> 3;
        const int m0 = by * 64, n0 = bx * 128;
        const int warp_m = wid & 1, warp_n = wid >> 1;   // 2x4 warps, 32x32

        const int r = tid >> 3;
        const int o16 = (tid & 7) << 4;
        const int c8 = (tid & 7) << 3;

        float acc[2][4][4];
#pragma unroll
        for (int i = 0; i < 2; i++)
#pragma unroll
            for (int j = 0; j < 4; j++)
#pragma unroll
                for (int k = 0; k < 4; k++) acc[i][j][k] = 0.f;

        const int lrow = lane & 15;
        const int lcol = (lane >> 4) << 4;
        uint32_t a_base[2], b_base[2];
#pragma unroll
        for (int mt = 0; mt < 2; mt++)
            a_base[mt] = (uint32_t)((warp_m * 32 + mt * 16 + lrow) * 128 + lcol);
#pragma unroll
        for (int nh = 0; nh < 2; nh++)
            b_base[nh] = (uint32_t)((warp_n * 32 + nh * 16 + lrow) * 128 + lcol);

#define LOAD_STAGE_SML(chunk, stage)                                               \
    do {                                                                           \
        uint32_t sA = sb + (stage) * SML_ASTG;                                     \
        uint32_t sB = sb + STAGES * SML_ASTG + (stage) * SML_BSTG;                 \
        int k0 = (chunk) * BK;                                                     \
        _Pragma("unroll") for (int t = 0; t < 2; t++) {                            \
            int rr = r + t * 32;                                                   \
            cp16(sA + SWZ((uint32_t)(rr * 128 + o16)),                             \
                 Asg + (size_t)(m0 + rr) * K + k0 + c8);                           \
        }                                                                          \
        _Pragma("unroll") for (int t = 0; t < 4; t++) {                            \
            int rr = r + t * 32;                                                   \
            cp16(sB + SWZ((uint32_t)(rr * 128 + o16)),                             \
                 Bsg + (size_t)(n0 + rr) * K + k0 + c8);                           \
        }                                                                          \
        CP_COMMIT();                                                               \
    } while (0)

        LOAD_STAGE_SML(0, 0);
        LOAD_STAGE_SML(1, 1);

        const int nk = K / BK;  // 16
        for (int i = 0; i < nk; i++) {
            const int st = i % STAGES;
            if (i + 2 < nk) {
                asm volatile("cp.async.wait_group 1;" ::: "memory");
                __syncthreads();
                LOAD_STAGE_SML(i + 2, (i + 2) % STAGES);
            } else {
                asm volatile("cp.async.wait_group 0;" ::: "memory");
                __syncthreads();
            }
            const uint32_t sA = sb + st * SML_ASTG;
            const uint32_t sB = sb + STAGES * SML_ASTG + st * SML_BSTG;
#pragma unroll
            for (int ks = 0; ks < 4; ks++) {
                uint32_t a[2][4], b[2][4];
#pragma unroll
                for (int nh = 0; nh < 2; nh++)
                    ldsm4(b[nh], sB + SWZ(b_base[nh] + (uint32_t)(ks * 32)));
#pragma unroll
                for (int mt = 0; mt < 2; mt++)
                    ldsm4(a[mt], sA + SWZ(a_base[mt] + (uint32_t)(ks * 32)));
#pragma unroll
                for (int mt = 0; mt < 2; mt++)
#pragma unroll
                    for (int nt = 0; nt < 4; nt++)
                        mma_f16(acc[mt][nt], a[mt], b[nt >> 1][nt & 1], b[nt >> 1][(nt & 1) + 2]);
            }
        }
#undef LOAD_STAGE_SML

        const int mrow = lane >> 2;
        const int mcol = (lane & 3) << 1;
#pragma unroll
        for (int mt = 0; mt < 2; mt++) {
#pragma unroll
            for (int nt = 0; nt < 4; nt++) {
                int row = m0 + warp_m * 32 + mt * 16 + mrow;
                int col = n0 + warp_n * 32 + nt * 8 + mcol;
                *(__half2*)&Csg[(size_t)row * ldc + col] =
                    __floats2half2_rn(acc[mt][nt][0], acc[mt][nt][1]);
                *(__half2*)&Csg[(size_t)(row + 8) * ldc + col] =
                    __floats2half2_rn(acc[mt][nt][2], acc[mt][nt][3]);
            }
        }
    } else {
        // ---- transpose branch ----
        float (*tile)[33] = (float(*)[33])smem;   // [128][33] = 16.9KB
        const int bb = blockIdx.x - SML_BLOCKS;
        const int bxx = bb % 6;                   // tn tile (768/128)
        const int byy = (bb / 6) & 31;            // c tile (1024/32)
        const int bz = bb / (6 * 32);             // batch
        const int c0 = byy * 32;
        const int tn0 = bxx * 128;
        const int lane = tid & 31, wid = tid >> 5;

#pragma unroll
        for (int p = 0; p < 4; p++) {
            const int c = wid + p * 8;
            float4 v = *(const float4*)(x + ((size_t)bz * C_ + c0 + c) * TN_ + tn0 + lane * 4);
            tile[lane * 4 + 0][c] = v.x;
            tile[lane * 4 + 1][c] = v.y;
            tile[lane * 4 + 2][c] = v.z;
            tile[lane * 4 + 3][c] = v.w;
        }
        __syncthreads();

        const int cc = (lane & 7) * 4;
        const int tnw = wid * 4 + (lane >> 3);
#pragma unroll
        for (int p = 0; p < 4; p++) {
            const int tn = tnw + p * 32;
            __half2 h01 = __floats2half2_rn(tile[tn][cc + 0], tile[tn][cc + 1]);
            __half2 h23 = __floats2half2_rn(tile[tn][cc + 2], tile[tn][cc + 3]);
            uint2 st;
            st.x = *(uint32_t*)&h01;
            st.y = *(uint32_t*)&h23;
            *(uint2*)(g_feat + ((size_t)bz * TN_ + tn0 + tn) * NF_ + c0 + cc) = st;
        }
    }
}

// ---------------------------------------------------------------------------
// Fused prep: blocks 0-2047 round wt/wp -> half; 2048-3071 transpose wg -> half
// (into g_BigB rows 1024+); 3072-3199 bias cross-term vectors (fp32 exact).
// ---------------------------------------------------------------------------
__global__ void prep_w(const float* __restrict__ wt, const float* __restrict__ wp,
                       const float* __restrict__ wg,
                       const float* __restrict__ bt, const float* __restrict__ bp) {
    const int bi = blockIdx.x;
    const int tid = threadIdx.x;
    if (bi < 2048) {
        const float4* in = (bi < 1024) ? (const float4*)wt : (const float4*)wp;
        __half* outp = (bi < 1024) ? g_wtr : g_wpr;
        const int i = (bi & 1023) * 256 + tid;
        float4 v = in[i];
        __half2 h01 = __floats2half2_rn(v.x, v.y);
        __half2 h23 = __floats2half2_rn(v.z, v.w);
        uint2 st;
        st.x = *(uint32_t*)&h01;
        st.y = *(uint32_t*)&h23;
        *(uint2*)(outp + (size_t)i * 4) = st;
    } else if (bi < 3072) {
        __shared__ float tile[32][33];
        const int bb = bi - 2048;
        const int k0 = (bb >> 5) * 32;
        const int n0 = (bb & 31) * 32;
        const int tx = tid & 31, ty = tid >> 5;
#pragma unroll
        for (int i = 0; i < 32; i += 8)
            tile[ty + i][tx] = wg[(size_t)(k0 + ty + i) * NF_ + n0 + tx];
        __syncthreads();
        __half* dst = g_BigB + (size_t)NF_ * NF_;
#pragma unroll
        for (int i = 0; i < 32; i += 8)
            dst[(size_t)(n0 + ty + i) * NF_ + k0 + tx] = __float2half_rn(tile[tx][ty + i]);
    } else {
        const int lane = tid & 31, warp = tid >> 5;
        const int c = (bi - 3072) * 8 + warp;
        const float* wtr = wt + (size_t)c * NF_;
        const float* wpr = wp + (size_t)c * NF_;
        float a = 0.f, b2 = 0.f;
#pragma unroll
        for (int i = 0; i < 32; i++) {
            const int k = lane + 32 * i;
            a  += wtr[k] * bp[k];
            b2 += wpr[k] * bt[k];
        }
#pragma unroll
        for (int o = 16; o > 0; o >>= 1) {
            a  += __shfl_xor_sync(0xffffffffu, a, o);
            b2 += __shfl_xor_sync(0xffffffffu, b2, o);
        }
        if (lane == 0) { g_vtp[c] = a; g_vpt[c] = b2; }
        if (bi == 3072 && warp == 0) {
            float s = 0.f;
#pragma unroll
            for (int i = 0; i < 32; i++) {
                const int k = lane + 32 * i;
                s += bt[k] * bp[k];
            }
#pragma unroll
            for (int o = 16; o > 0; o >>= 1) s += __shfl_xor_sync(0xffffffffu, s, o);
            if (lane == 0) g_bb[0] = s;
        }
    }
}

// ---------------------------------------------------------------------------
__device__ __forceinline__ float blockSum512(float v, float* red) {
    const int lane = threadIdx.x & 31, warp = threadIdx.x >> 5;
#pragma unroll
    for (int o = 16; o > 0; o >>= 1) v += __shfl_xor_sync(0xffffffffu, v, o);
    if (lane == 0) red[warp] = v;
    __syncthreads();
    if (threadIdx.x == 0) {
        float s = 0.f;
        for (int i = 0; i < 16; i++) s += red[i];
        red[16] = s;
    }
    __syncthreads();
    float r = red[16];
    __syncthreads();
    return r;
}

__device__ __forceinline__ float dot4(float4 a, float4 b) {
    return a.x * b.x + a.y * b.y + a.z * b.z + a.w * b.w;
}

// Per-frame: logits, mask, softmax, agg, LN, ReLU. feat staged in smem (fp32).
__global__ void __launch_bounds__(512) frame_kernel(const float* __restrict__ Abox,
                                                    const float* __restrict__ ln_w,
                                                    const float* __restrict__ ln_b,
                                                    float* __restrict__ out,
                                                    float* __restrict__ rg_out) {
    extern __shared__ float sfm[];   // [12][1024] fp32 feat for this frame
    const int f = blockIdx.x;
    const int tid = threadIdx.x;
    const int lane = tid & 31, warp = tid >> 5;

    __shared__ float px[12], py[12], sqs[12];
    __shared__ float s_u[12], s_v[12];
    __shared__ float s_rg[12][12];
    __shared__ float red[17];

    if (tid < 12) {
        const float* bx = Abox + ((size_t)f * 12 + tid) * 4;
        float cx = (bx[0] + bx[2]) * 0.5f;
        float cy = (bx[1] + bx[3]) * 0.5f;
        px[tid] = cx; py[tid] = cy; sqs[tid] = cx * cx + cy * cy;
    }

    {
        const __half2* src = (const __half2*)(g_feat + (size_t)f * 12 * NF_);
#pragma unroll
        for (int i = 0; i < 12; i++) {
            const int idx = tid + i * 512;
            float2 v = __half22float2(src[idx]);
            sfm[idx * 2] = v.x;
            sfm[idx * 2 + 1] = v.y;
        }
    }
    __syncthreads();

    if (warp < 12) {
        const float4* frow = (const float4*)(sfm + warp * NF_);
        const float4* vt4 = (const float4*)g_vtp;
        const float4* vp4 = (const float4*)g_vpt;
        float ua = 0.f, va = 0.f;
#pragma unroll
        for (int k = 0; k < 8; k++) {
            float4 fv = frow[lane + 32 * k];
            ua += dot4(fv, vt4[lane + 32 * k]);
            va += dot4(fv, vp4[lane + 32 * k]);
        }
#pragma unroll
        for (int o = 16; o > 0; o >>= 1) {
            ua += __shfl_xor_sync(0xffffffffu, ua, o);
            va += __shfl_xor_sync(0xffffffffu, va, o);
        }
        if (lane == 0) { s_u[warp] = ua; s_v[warp] = va; }
    }
    __syncthreads();

    if (warp < 12) {
        const int n = warp;
        const uint2* tM2 = (const uint2*)(g_TG + ((size_t)f * 12 + n) * NB_);
        float4 tr[8];
#pragma unroll
        for (int k = 0; k < 8; k++) {
            uint2 u = tM2[lane + 32 * k];
            float2 f0 = __half22float2(*(__half2*)&u.x);
            float2 f1 = __half22float2(*(__half2*)&u.y);
            tr[k] = make_float4(f0.x, f0.y, f1.x, f1.y);
        }
        float lg[12];
#pragma unroll
        for (int m = 0; m < 12; m++) {
            const float4* fm4 = (const float4*)(sfm + m * NF_);
            float a = 0.f;
#pragma unroll
            for (int k = 0; k < 8; k++) a += dot4(tr[k], fm4[lane + 32 * k]);
#pragma unroll
            for (int o = 16; o > 0; o >>= 1) a += __shfl_xor_sync(0xffffffffu, a, o);
            lg[m] = a;
        }
        if (lane == 0) {
            const float bb = g_bb[0];
            const float scale = 0.03125f;
            float e[12];
            bool msk[12];
            float mx = -INFINITY;
#pragma unroll
            for (int m = 0; m < 12; m++) {
                float d2 = sqs[n] - 2.f * (px[n] * px[m] + py[n] * py[m]) + sqs[m];
                d2 = fmaxf(d2, 0.f);
                float dist = sqrtf(d2);
                msk[m] = (dist > 0.4f);
                float v = (lg[m] + s_u[n] + s_v[m] + bb) * scale;
                e[m] = v;
                if (!msk[m]) mx = fmaxf(mx, v);
            }
            float se = 0.f;
#pragma unroll
            for (int m = 0; m < 12; m++) {
                float ev = msk[m] ? 0.f : expf(e[m] - mx);
                e[m] = ev;
                se += ev;
            }
            float inv = 1.f / se;
#pragma unroll
            for (int m = 0; m < 12; m++) {
                float r = e[m] * inv;
                s_rg[n][m] = r;
                if (rg_out) rg_out[((size_t)f * 12 + n) * 12 + m] = r;
            }
        }
    }
    __syncthreads();

    float2 aggv[12];
    {
        float2 gv[12];
#pragma unroll
        for (int m = 0; m < 12; m++) {
            const __half2* g2 = (const __half2*)(g_TG + ((size_t)f * 12 + m) * NB_ + NF_);
            gv[m] = __half22float2(g2[tid]);
        }
#pragma unroll
        for (int n = 0; n < 12; n++) {
            float ax = 0.f, ay = 0.f;
#pragma unroll
            for (int m = 0; m < 12; m++) {
                float w = s_rg[n][m];
                ax += w * gv[m].x;
                ay += w * gv[m].y;
            }
            aggv[n] = make_float2(ax, ay);
        }
    }
    float lsum = 0.f;
#pragma unroll
    for (int n = 0; n < 12; n++) lsum += aggv[n].x + aggv[n].y;
    const float mu = blockSum512(lsum, red) * (1.f / 12288.f);

    float lsq = 0.f;
#pragma unroll
    for (int n = 0; n < 12; n++) {
        float dx = aggv[n].x - mu, dy = aggv[n].y - mu;
        lsq += dx * dx + dy * dy;
    }
    const float var = blockSum512(lsq, red) * (1.f / 12288.f);
    const float rstd = rsqrtf(var + 1e-5f);

    const float2* lw2 = (const float2*)ln_w;
    const float2* lb2 = (const float2*)ln_b;
    float2* out2 = (float2*)out;
#pragma unroll
    for (int n = 0; n < 12; n++) {
        float2 w = lw2[n * 512 + tid];
        float2 b = lb2[n * 512 + tid];
        float yx = (aggv[n].x - mu) * rstd * w.x + b.x;
        float yy = (aggv[n].y - mu) * rstd * w.y + b.y;
        out2[((size_t)f * 12 + n) * 512 + tid] = make_float2(fmaxf(yx, 0.f), fmaxf(yy, 0.f));
    }
}

// ---------------------------------------------------------------------------
extern "C" void kernel_launch(void* const* d_in, const int* in_sizes, int n_in,
                              void* d_out, int out_size) {
    const float* x  = (const float*)d_in[0];
    const float* A  = (const float*)d_in[1];
    const float* wt = (const float*)d_in[2];
    const float* bt = (const float*)d_in[3];
    const float* wp = (const float*)d_in[4];
    const float* bp = (const float*)d_in[5];
    const float* wg = (const float*)d_in[6];
    const float* lw = (const float*)d_in[7];
    const float* lb = (const float*)d_in[8];

    float* out = (float*)d_out;
    float* rg = (out_size >= (int)(ROWS_ * NF_ + BT_ * N_ * N_))
                    ? out + (size_t)ROWS_ * NF_
                    : nullptr;

    __half *feat, *TG, *BigB, *wtr, *wpr;
    cudaGetSymbolAddress((void**)&feat, g_feat);
    cudaGetSymbolAddress((void**)&TG, g_TG);
    cudaGetSymbolAddress((void**)&BigB, g_BigB);
    cudaGetSymbolAddress((void**)&wtr, g_wtr);
    cudaGetSymbolAddress((void**)&wpr, g_wpr);

    cudaFuncSetAttribute(fused_sg_tx,
                         cudaFuncAttributeMaxDynamicSharedMemorySize, SML_SMEM);
    cudaFuncSetAttribute(mma_gemm_big,
                         cudaFuncAttributeMaxDynamicSharedMemorySize, BIG_SMEM);
    cudaFuncSetAttribute(frame_kernel,
                         cudaFuncAttributeMaxDynamicSharedMemorySize, 49152);

    // 4 launches: prep -> [small GEMM + transpose fused] -> big GEMM -> frame
    prep_w<<<3200, 256>>>(wt, wp, wg, bt, bp);                               // 1
    fused_sg_tx<<<SML_BLOCKS + TX_BLOCKS, 256, SML_SMEM>>>(                  // 2
        wpr, wtr, BigB, x);
    mma_gemm_big<<<dim3(NB_ / 128, ROWS_ / 128), 128, BIG_SMEM>>>(           // 3
        feat, BigB, TG);
    frame_kernel<<<BT_, 512, 49152>>>(A, lw, lb, out, rg);                   // 4
}

// round 13
// speedup vs baseline: 2.0432x; 1.0820x over previous
#include <cuda_runtime.h>
#include <cuda_fp16.h>
#include <math.h>
#include <stdint.h>

// Problem constants
#define B_    16
#define C_    1024
#define T_    64
#define N_    12
#define BT_   (B_ * T_)       // 1024 frames
#define NF_   1024
#define ROWS_ (BT_ * N_)      // 12288
#define TN_   (T_ * N_)       // 768
#define NB_   2048            // fused B rows: [MwT | wg^T]

// Scratch (static device globals)
__device__ __half g_feat[ROWS_ * NF_];   // feat, rn-rounded to fp16
__device__ __half g_TG[ROWS_ * NB_];     // [tM | G] fused output (fp16)
__device__ __half g_BigB[NB_ * NF_];     // rows 0-1023: MwT, 1024-2047: wg^T
__device__ __half g_wtr[NF_ * NF_];      // Wtheta rounded to fp16
__device__ __half g_wpr[NF_ * NF_];      // Wphi rounded to fp16
__device__ float  g_vtp[NF_];
__device__ float  g_vpt[NF_];
__device__ float  g_bb[1];

// ---------------------------------------------------------------------------
// Helpers (baseline PTX only)
// ---------------------------------------------------------------------------
__device__ __forceinline__ uint32_t smem_u32(const void* p) {
    uint32_t a;
    asm("{ .reg .u64 t; cvta.to.shared.u64 t, %1; cvt.u32.u64 %0, t; }" : "=r"(a) : "l"(p));
    return a;
}
__device__ __forceinline__ void cp16(uint32_t s, const void* g) {
    asm volatile("cp.async.cg.shared.global [%0], [%1], 16;" :: "r"(s), "l"(g) : "memory");
}
#define CP_COMMIT() asm volatile("cp.async.commit_group;" ::: "memory")
#define SWZ(x) ((x) ^ (((x) >> 3) & 0x70))

__device__ __forceinline__ void ldsm4(uint32_t* r, uint32_t addr) {
    asm volatile("ldmatrix.sync.aligned.m8n8.x4.shared.b16 {%0,%1,%2,%3}, [%4];"
                 : "=r"(r[0]), "=r"(r[1]), "=r"(r[2]), "=r"(r[3]) : "r"(addr));
}
// fp16 MMA, fp32 accumulate
__device__ __forceinline__ void mma_f16(float* c, const uint32_t* a, uint32_t b0, uint32_t b1) {
    asm volatile("mma.sync.aligned.m16n8k16.row.col.f32.f16.f16.f32 "
                 "{%0,%1,%2,%3}, {%4,%5,%6,%7}, {%8,%9}, {%0,%1,%2,%3};"
                 : "+f"(c[0]), "+f"(c[1]), "+f"(c[2]), "+f"(c[3])
                 : "r"(a[0]), "r"(a[1]), "r"(a[2]), "r"(a[3]), "r"(b0), "r"(b1));
}

#define BK 64          // fp16: 64 halves = 128B rows
#define STAGES 3

// ---------------------------------------------------------------------------
// Big GEMM (fp16): 128 thr (4 warps), CTA 128x128, warp 64x64, 3 stages,
// 2 CTA/SM. C[m,n] = sum_k A[m,k]*Bm[n,k]; half in, half out.
// ---------------------------------------------------------------------------
#define BIG_STG 16384
#define BIG_SMEM (STAGES * 2 * BIG_STG)   // 98304

__global__ void __launch_bounds__(128, 2) mma_gemm_big(const __half* __restrict__ A,
                                                       const __half* __restrict__ Bm,
                                                       __half* __restrict__ C) {
    const int K = NF_, ldc = NB_;
    extern __shared__ char smem[];
    const uint32_t sb = smem_u32(smem);
    const int tid = threadIdx.x, lane = tid & 31, wid = tid >> 5;
    const int m0 = blockIdx.y * 128, n0 = blockIdx.x * 128;
    const int warp_m = wid & 1, warp_n = wid >> 1;   // 2x2 warps, 64x64 each

    const int r = tid >> 3;
    const int o16 = (tid & 7) << 4;
    const int c8 = (tid & 7) << 3;

    float acc[4][8][4];
#pragma unroll
    for (int i = 0; i < 4; i++)
#pragma unroll
        for (int j = 0; j < 8; j++)
#pragma unroll
            for (int k = 0; k < 4; k++) acc[i][j][k] = 0.f;

    const int lrow = lane & 15;
    const int lcol = (lane >> 4) << 4;
    uint32_t a_base[4], b_base[4];
#pragma unroll
    for (int mt = 0; mt < 4; mt++)
        a_base[mt] = (uint32_t)((warp_m * 64 + mt * 16 + lrow) * 128 + lcol);
#pragma unroll
    for (int nh = 0; nh < 4; nh++)
        b_base[nh] = (uint32_t)((warp_n * 64 + nh * 16 + lrow) * 128 + lcol);

#define LOAD_STAGE_BIG(chunk, stage)                                               \
    do {                                                                           \
        uint32_t sA = sb + (stage) * BIG_STG;                                      \
        uint32_t sB = sb + STAGES * BIG_STG + (stage) * BIG_STG;                   \
        int k0 = (chunk) * BK;                                                     \
        _Pragma("unroll") for (int t = 0; t < 8; t++) {                            \
            int rr = r + t * 16;                                                   \
            cp16(sA + SWZ((uint32_t)(rr * 128 + o16)),                             \
                 A + (size_t)(m0 + rr) * K + k0 + c8);                             \
        }                                                                          \
        _Pragma("unroll") for (int t = 0; t < 8; t++) {                            \
            int rr = r + t * 16;                                                   \
            cp16(sB + SWZ((uint32_t)(rr * 128 + o16)),                             \
                 Bm + (size_t)(n0 + rr) * K + k0 + c8);                            \
        }                                                                          \
        CP_COMMIT();                                                               \
    } while (0)

    LOAD_STAGE_BIG(0, 0);
    LOAD_STAGE_BIG(1, 1);

    const int nk = K / BK;  // 16
    for (int i = 0; i < nk; i++) {
        const int st = i % STAGES;
        if (i + 2 < nk) {
            asm volatile("cp.async.wait_group 1;" ::: "memory");
            __syncthreads();
            LOAD_STAGE_BIG(i + 2, (i + 2) % STAGES);
        } else {
            asm volatile("cp.async.wait_group 0;" ::: "memory");
            __syncthreads();
        }
        const uint32_t sA = sb + st * BIG_STG;
        const uint32_t sB = sb + STAGES * BIG_STG + st * BIG_STG;
#pragma unroll
        for (int ks = 0; ks < 4; ks++) {     // 4 x k16 per BK=64 chunk
            uint32_t a[4][4], b[4][4];
#pragma unroll
            for (int nh = 0; nh < 4; nh++)
                ldsm4(b[nh], sB + SWZ(b_base[nh] + (uint32_t)(ks * 32)));
#pragma unroll
            for (int mt = 0; mt < 4; mt++)
                ldsm4(a[mt], sA + SWZ(a_base[mt] + (uint32_t)(ks * 32)));
#pragma unroll
            for (int mt = 0; mt < 4; mt++)
#pragma unroll
                for (int nt = 0; nt < 8; nt++)
                    mma_f16(acc[mt][nt], a[mt], b[nt >> 1][nt & 1], b[nt >> 1][(nt & 1) + 2]);
        }
    }
#undef LOAD_STAGE_BIG

    const int mrow = lane >> 2;
    const int mcol = (lane & 3) << 1;
#pragma unroll
    for (int mt = 0; mt < 4; mt++) {
#pragma unroll
        for (int nt = 0; nt < 8; nt++) {
            int row = m0 + warp_m * 64 + mt * 16 + mrow;
            int col = n0 + warp_n * 64 + nt * 8 + mcol;
            *(__half2*)&C[(size_t)row * ldc + col] =
                __floats2half2_rn(acc[mt][nt][0], acc[mt][nt][1]);
            *(__half2*)&C[(size_t)(row + 8) * ldc + col] =
                __floats2half2_rn(acc[mt][nt][2], acc[mt][nt][3]);
        }
    }
}

// ---------------------------------------------------------------------------
// FUSED: small GEMM (blocks 0..127) + transpose_x (blocks 128..3199).
// ---------------------------------------------------------------------------
#define SML_ASTG 8192
#define SML_BSTG 16384
#define SML_SMEM (STAGES * (SML_ASTG + SML_BSTG))   // 73728
#define SML_BLOCKS 128
#define TX_BLOCKS (6 * 32 * 16)                      // 3072

__global__ void __launch_bounds__(256) fused_sg_tx(const __half* __restrict__ Asg,
                                                   const __half* __restrict__ Bsg,
                                                   __half* __restrict__ Csg,
                                                   const float* __restrict__ x) {
    extern __shared__ char smem[];
    const int tid = threadIdx.x;

    if (blockIdx.x < SML_BLOCKS) {
        // ---- small GEMM branch ----
        const int K = NF_, ldc = NF_;
        const uint32_t sb = smem_u32(smem);
        const int lane = tid & 31, wid = tid >> 5;
        const int bx = blockIdx.x & 7, by = blockIdx.x >> 3;
        const int m0 = by * 64, n0 = bx * 128;
        const int warp_m = wid & 1, warp_n = wid >> 1;   // 2x4 warps, 32x32

        const int r = tid >> 3;
        const int o16 = (tid & 7) << 4;
        const int c8 = (tid & 7) << 3;

        float acc[2][4][4];
#pragma unroll
        for (int i = 0; i < 2; i++)
#pragma unroll
            for (int j = 0; j < 4; j++)
#pragma unroll
                for (int k = 0; k < 4; k++) acc[i][j][k] = 0.f;

        const int lrow = lane & 15;
        const int lcol = (lane >> 4) << 4;
        uint32_t a_base[2], b_base[2];
#pragma unroll
        for (int mt = 0; mt < 2; mt++)
            a_base[mt] = (uint32_t)((warp_m * 32 + mt * 16 + lrow) * 128 + lcol);
#pragma unroll
        for (int nh = 0; nh < 2; nh++)
            b_base[nh] = (uint32_t)((warp_n * 32 + nh * 16 + lrow) * 128 + lcol);

#define LOAD_STAGE_SML(chunk, stage)                                               \
    do {                                                                           \
        uint32_t sA = sb + (stage) * SML_ASTG;                                     \
        uint32_t sB = sb + STAGES * SML_ASTG + (stage) * SML_BSTG;                 \
        int k0 = (chunk) * BK;                                                     \
        _Pragma("unroll") for (int t = 0; t < 2; t++) {                            \
            int rr = r + t * 32;                                                   \
            cp16(sA + SWZ((uint32_t)(rr * 128 + o16)),                             \
                 Asg + (size_t)(m0 + rr) * K + k0 + c8);                           \
        }                                                                          \
        _Pragma("unroll") for (int t = 0; t < 4; t++) {                            \
            int rr = r + t * 32;                                                   \
            cp16(sB + SWZ((uint32_t)(rr * 128 + o16)),                             \
                 Bsg + (size_t)(n0 + rr) * K + k0 + c8);                           \
        }                                                                          \
        CP_COMMIT();                                                               \
    } while (0)

        LOAD_STAGE_SML(0, 0);
        LOAD_STAGE_SML(1, 1);

        const int nk = K / BK;  // 16
        for (int i = 0; i < nk; i++) {
            const int st = i % STAGES;
            if (i + 2 < nk) {
                asm volatile("cp.async.wait_group 1;" ::: "memory");
                __syncthreads();
                LOAD_STAGE_SML(i + 2, (i + 2) % STAGES);
            } else {
                asm volatile("cp.async.wait_group 0;" ::: "memory");
                __syncthreads();
            }
            const uint32_t sA = sb + st * SML_ASTG;
            const uint32_t sB = sb + STAGES * SML_ASTG + st * SML_BSTG;
#pragma unroll
            for (int ks = 0; ks < 4; ks++) {
                uint32_t a[2][4], b[2][4];
#pragma unroll
                for (int nh = 0; nh < 2; nh++)
                    ldsm4(b[nh], sB + SWZ(b_base[nh] + (uint32_t)(ks * 32)));
#pragma unroll
                for (int mt = 0; mt < 2; mt++)
                    ldsm4(a[mt], sA + SWZ(a_base[mt] + (uint32_t)(ks * 32)));
#pragma unroll
                for (int mt = 0; mt < 2; mt++)
#pragma unroll
                    for (int nt = 0; nt < 4; nt++)
                        mma_f16(acc[mt][nt], a[mt], b[nt >> 1][nt & 1], b[nt >> 1][(nt & 1) + 2]);
            }
        }
#undef LOAD_STAGE_SML

        const int mrow = lane >> 2;
        const int mcol = (lane & 3) << 1;
#pragma unroll
        for (int mt = 0; mt < 2; mt++) {
#pragma unroll
            for (int nt = 0; nt < 4; nt++) {
                int row = m0 + warp_m * 32 + mt * 16 + mrow;
                int col = n0 + warp_n * 32 + nt * 8 + mcol;
                *(__half2*)&Csg[(size_t)row * ldc + col] =
                    __floats2half2_rn(acc[mt][nt][0], acc[mt][nt][1]);
                *(__half2*)&Csg[(size_t)(row + 8) * ldc + col] =
                    __floats2half2_rn(acc[mt][nt][2], acc[mt][nt][3]);
            }
        }
    } else {
        // ---- transpose branch ----
        float (*tile)[33] = (float(*)[33])smem;
        const int bb = blockIdx.x - SML_BLOCKS;
        const int bxx = bb % 6;
        const int byy = (bb / 6) & 31;
        const int bz = bb / (6 * 32);
        const int c0 = byy * 32;
        const int tn0 = bxx * 128;
        const int lane = tid & 31, wid = tid >> 5;

#pragma unroll
        for (int p = 0; p < 4; p++) {
            const int c = wid + p * 8;
            float4 v = *(const float4*)(x + ((size_t)bz * C_ + c0 + c) * TN_ + tn0 + lane * 4);
            tile[lane * 4 + 0][c] = v.x;
            tile[lane * 4 + 1][c] = v.y;
            tile[lane * 4 + 2][c] = v.z;
            tile[lane * 4 + 3][c] = v.w;
        }
        __syncthreads();

        const int cc = (lane & 7) * 4;
        const int tnw = wid * 4 + (lane >> 3);
#pragma unroll
        for (int p = 0; p < 4; p++) {
            const int tn = tnw + p * 32;
            __half2 h01 = __floats2half2_rn(tile[tn][cc + 0], tile[tn][cc + 1]);
            __half2 h23 = __floats2half2_rn(tile[tn][cc + 2], tile[tn][cc + 3]);
            uint2 st;
            st.x = *(uint32_t*)&h01;
            st.y = *(uint32_t*)&h23;
            *(uint2*)(g_feat + ((size_t)bz * TN_ + tn0 + tn) * NF_ + c0 + cc) = st;
        }
    }
}

// ---------------------------------------------------------------------------
// Fused prep: blocks 0-2047 round wt/wp -> half; 2048-3071 transpose wg -> half;
// 3072-3199 bias cross-term vectors (fp32 exact).
// ---------------------------------------------------------------------------
__global__ void prep_w(const float* __restrict__ wt, const float* __restrict__ wp,
                       const float* __restrict__ wg,
                       const float* __restrict__ bt, const float* __restrict__ bp) {
    const int bi = blockIdx.x;
    const int tid = threadIdx.x;
    if (bi < 2048) {
        const float4* in = (bi < 1024) ? (const float4*)wt : (const float4*)wp;
        __half* outp = (bi < 1024) ? g_wtr : g_wpr;
        const int i = (bi & 1023) * 256 + tid;
        float4 v = in[i];
        __half2 h01 = __floats2half2_rn(v.x, v.y);
        __half2 h23 = __floats2half2_rn(v.z, v.w);
        uint2 st;
        st.x = *(uint32_t*)&h01;
        st.y = *(uint32_t*)&h23;
        *(uint2*)(outp + (size_t)i * 4) = st;
    } else if (bi < 3072) {
        __shared__ float tile[32][33];
        const int bb = bi - 2048;
        const int k0 = (bb >> 5) * 32;
        const int n0 = (bb & 31) * 32;
        const int tx = tid & 31, ty = tid >> 5;
#pragma unroll
        for (int i = 0; i < 32; i += 8)
            tile[ty + i][tx] = wg[(size_t)(k0 + ty + i) * NF_ + n0 + tx];
        __syncthreads();
        __half* dst = g_BigB + (size_t)NF_ * NF_;
#pragma unroll
        for (int i = 0; i < 32; i += 8)
            dst[(size_t)(n0 + ty + i) * NF_ + k0 + tx] = __float2half_rn(tile[tx][ty + i]);
    } else {
        const int lane = tid & 31, warp = tid >> 5;
        const int c = (bi - 3072) * 8 + warp;
        const float* wtr = wt + (size_t)c * NF_;
        const float* wpr = wp + (size_t)c * NF_;
        float a = 0.f, b2 = 0.f;
#pragma unroll
        for (int i = 0; i < 32; i++) {
            const int k = lane + 32 * i;
            a  += wtr[k] * bp[k];
            b2 += wpr[k] * bt[k];
        }
#pragma unroll
        for (int o = 16; o > 0; o >>= 1) {
            a  += __shfl_xor_sync(0xffffffffu, a, o);
            b2 += __shfl_xor_sync(0xffffffffu, b2, o);
        }
        if (lane == 0) { g_vtp[c] = a; g_vpt[c] = b2; }
        if (bi == 3072 && warp == 0) {
            float s = 0.f;
#pragma unroll
            for (int i = 0; i < 32; i++) {
                const int k = lane + 32 * i;
                s += bt[k] * bp[k];
            }
#pragma unroll
            for (int o = 16; o > 0; o >>= 1) s += __shfl_xor_sync(0xffffffffu, s, o);
            if (lane == 0) g_bb[0] = s;
        }
    }
}

// ---------------------------------------------------------------------------
// Combined block reduction of two values (one smem round).
// ---------------------------------------------------------------------------
__device__ __forceinline__ float2 blockSum2(float v1, float v2, float* red) {
    const int lane = threadIdx.x & 31, warp = threadIdx.x >> 5;
#pragma unroll
    for (int o = 16; o > 0; o >>= 1) {
        v1 += __shfl_xor_sync(0xffffffffu, v1, o);
        v2 += __shfl_xor_sync(0xffffffffu, v2, o);
    }
    if (lane == 0) { red[warp] = v1; red[warp + 16] = v2; }
    __syncthreads();
    if (threadIdx.x == 0) {
        float s1 = 0.f, s2 = 0.f;
        for (int i = 0; i < 16; i++) { s1 += red[i]; s2 += red[i + 16]; }
        red[32] = s1; red[33] = s2;
    }
    __syncthreads();
    float2 r = make_float2(red[32], red[33]);
    __syncthreads();
    return r;
}

// Per-frame: logits, mask, softmax, agg, LN, ReLU. feat staged in smem (fp16).
// 64-reg cap -> 2 CTA/SM.
__global__ void __launch_bounds__(512, 2) frame_kernel(const float* __restrict__ Abox,
                                                       const float* __restrict__ ln_w,
                                                       const float* __restrict__ ln_b,
                                                       float* __restrict__ out,
                                                       float* __restrict__ rg_out) {
    extern __shared__ char smraw[];
    __half* sfm = (__half*)smraw;    // [12][1024] fp16 feat for this frame (24KB)
    const int f = blockIdx.x;
    const int tid = threadIdx.x;
    const int lane = tid & 31, warp = tid >> 5;

    __shared__ float px[12], py[12], sqs[12];
    __shared__ float s_u[12], s_v[12];
    __shared__ float s_rg[12][12];
    __shared__ float red[34];

    if (tid < 12) {
        const float* bx = Abox + ((size_t)f * 12 + tid) * 4;
        float cx = (bx[0] + bx[2]) * 0.5f;
        float cy = (bx[1] + bx[3]) * 0.5f;
        px[tid] = cx; py[tid] = cy; sqs[tid] = cx * cx + cy * cy;
    }

    // stage feat_f (12 x 1024 halves = 6144 half2) into smem, raw copy
    {
        const uint32_t* src = (const uint32_t*)(g_feat + (size_t)f * 12 * NF_);
        uint32_t* dst = (uint32_t*)sfm;
#pragma unroll
        for (int i = 0; i < 12; i++)
            dst[tid + i * 512] = src[tid + i * 512];
    }
    __syncthreads();

    // phase 1: bias cross terms; feat from smem (half2 -> float)
    if (warp < 12) {
        const __half2* frow = (const __half2*)(sfm + warp * NF_);
        const float2* vt2 = (const float2*)g_vtp;
        const float2* vp2 = (const float2*)g_vpt;
        float ua = 0.f, va = 0.f;
#pragma unroll
        for (int k = 0; k < 16; k++) {
            float2 fv = __half22float2(frow[lane + 32 * k]);
            float2 t = vt2[lane + 32 * k];
            float2 p = vp2[lane + 32 * k];
            ua += fv.x * t.x + fv.y * t.y;
            va += fv.x * p.x + fv.y * p.y;
        }
#pragma unroll
        for (int o = 16; o > 0; o >>= 1) {
            ua += __shfl_xor_sync(0xffffffffu, ua, o);
            va += __shfl_xor_sync(0xffffffffu, va, o);
        }
        if (lane == 0) { s_u[warp] = ua; s_v[warp] = va; }
    }
    __syncthreads();

    // phase 2: logits; tM (half) from global, fm (half) from smem
    if (warp < 12) {
        const int n = warp;
        const uint2* tM2 = (const uint2*)(g_TG + ((size_t)f * 12 + n) * NB_);
        float4 tr[8];
#pragma unroll
        for (int k = 0; k < 8; k++) {
            uint2 u = tM2[lane + 32 * k];
            float2 f0 = __half22float2(*(__half2*)&u.x);
            float2 f1 = __half22float2(*(__half2*)&u.y);
            tr[k] = make_float4(f0.x, f0.y, f1.x, f1.y);
        }
        float lg[12];
#pragma unroll
        for (int m = 0; m < 12; m++) {
            const uint2* fm2 = (const uint2*)(sfm + m * NF_);
            float a = 0.f;
#pragma unroll
            for (int k = 0; k < 8; k++) {
                uint2 u = fm2[lane + 32 * k];
                float2 f0 = __half22float2(*(__half2*)&u.x);
                float2 f1 = __half22float2(*(__half2*)&u.y);
                a += tr[k].x * f0.x + tr[k].y * f0.y + tr[k].z * f1.x + tr[k].w * f1.y;
            }
#pragma unroll
            for (int o = 16; o > 0; o >>= 1) a += __shfl_xor_sync(0xffffffffu, a, o);
            lg[m] = a;
        }
        if (lane == 0) {
            const float bb = g_bb[0];
            const float scale = 0.03125f;
            float e[12];
            bool msk[12];
            float mx = -INFINITY;
#pragma unroll
            for (int m = 0; m < 12; m++) {
                float d2 = sqs[n] - 2.f * (px[n] * px[m] + py[n] * py[m]) + sqs[m];
                d2 = fmaxf(d2, 0.f);
                float dist = sqrtf(d2);
                msk[m] = (dist > 0.4f);
                float v = (lg[m] + s_u[n] + s_v[m] + bb) * scale;
                e[m] = v;
                if (!msk[m]) mx = fmaxf(mx, v);
            }
            float se = 0.f;
#pragma unroll
            for (int m = 0; m < 12; m++) {
                float ev = msk[m] ? 0.f : expf(e[m] - mx);
                e[m] = ev;
                se += ev;
            }
            float inv = 1.f / se;
#pragma unroll
            for (int m = 0; m < 12; m++) {
                float r = e[m] * inv;
                s_rg[n][m] = r;
                if (rg_out) rg_out[((size_t)f * 12 + n) * 12 + m] = r;
            }
        }
    }
    __syncthreads();

    // phase 3: agg = rg @ G_f; single-pass moments; LN + ReLU
    float2 aggv[12];
    float lsum = 0.f, lsq = 0.f;
    {
        float2 gv[12];
#pragma unroll
        for (int m = 0; m < 12; m++) {
            const __half2* g2 = (const __half2*)(g_TG + ((size_t)f * 12 + m) * NB_ + NF_);
            gv[m] = __half22float2(g2[tid]);
        }
#pragma unroll
        for (int n = 0; n < 12; n++) {
            float ax = 0.f, ay = 0.f;
#pragma unroll
            for (int m = 0; m < 12; m++) {
                float w = s_rg[n][m];
                ax += w * gv[m].x;
                ay += w * gv[m].y;
            }
            aggv[n] = make_float2(ax, ay);
            lsum += ax + ay;
            lsq += ax * ax + ay * ay;
        }
    }
    float2 mom = blockSum2(lsum, lsq, red);
    const float mu = mom.x * (1.f / 12288.f);
    const float var = mom.y * (1.f / 12288.f) - mu * mu;
    const float rstd = rsqrtf(var + 1e-5f);

    const float2* lw2 = (const float2*)ln_w;
    const float2* lb2 = (const float2*)ln_b;
    float2* out2 = (float2*)out;
#pragma unroll
    for (int n = 0; n < 12; n++) {
        float2 w = lw2[n * 512 + tid];
        float2 b = lb2[n * 512 + tid];
        float yx = (aggv[n].x - mu) * rstd * w.x + b.x;
        float yy = (aggv[n].y - mu) * rstd * w.y + b.y;
        out2[((size_t)f * 12 + n) * 512 + tid] = make_float2(fmaxf(yx, 0.f), fmaxf(yy, 0.f));
    }
}

// ---------------------------------------------------------------------------
extern "C" void kernel_launch(void* const* d_in, const int* in_sizes, int n_in,
                              void* d_out, int out_size) {
    const float* x  = (const float*)d_in[0];
    const float* A  = (const float*)d_in[1];
    const float* wt = (const float*)d_in[2];
    const float* bt = (const float*)d_in[3];
    const float* wp = (const float*)d_in[4];
    const float* bp = (const float*)d_in[5];
    const float* wg = (const float*)d_in[6];
    const float* lw = (const float*)d_in[7];
    const float* lb = (const float*)d_in[8];

    float* out = (float*)d_out;
    float* rg = (out_size >= (int)(ROWS_ * NF_ + BT_ * N_ * N_))
                    ? out + (size_t)ROWS_ * NF_
                    : nullptr;

    __half *feat, *TG, *BigB, *wtr, *wpr;
    cudaGetSymbolAddress((void**)&feat, g_feat);
    cudaGetSymbolAddress((void**)&TG, g_TG);
    cudaGetSymbolAddress((void**)&BigB, g_BigB);
    cudaGetSymbolAddress((void**)&wtr, g_wtr);
    cudaGetSymbolAddress((void**)&wpr, g_wpr);

    cudaFuncSetAttribute(fused_sg_tx,
                         cudaFuncAttributeMaxDynamicSharedMemorySize, SML_SMEM);
    cudaFuncSetAttribute(mma_gemm_big,
                         cudaFuncAttributeMaxDynamicSharedMemorySize, BIG_SMEM);
    cudaFuncSetAttribute(frame_kernel,
                         cudaFuncAttributeMaxDynamicSharedMemorySize, 24576);

    // 4 launches: prep -> [small GEMM + transpose fused] -> big GEMM -> frame
    prep_w<<<3200, 256>>>(wt, wp, wg, bt, bp);                               // 1
    fused_sg_tx<<<SML_BLOCKS + TX_BLOCKS, 256, SML_SMEM>>>(                  // 2
        wpr, wtr, BigB, x);
    mma_gemm_big<<<dim3(NB_ / 128, ROWS_ / 128), 128, BIG_SMEM>>>(           // 3
        feat, BigB, TG);
    frame_kernel<<<BT_, 512, 24576>>>(A, lw, lb, out, rg);                   // 4
}